// round 2
// baseline (speedup 1.0000x reference)
#include <cuda_runtime.h>
#include <math.h>

// Problem constants
#define D_MODEL 512
#define N_HEADS 8
#define DH      64
#define D_FF    2048
#define BATCH   4
#define SEQ     2048
#define NROWS   (BATCH*SEQ)   // 8192

// ---------------------------------------------------------------------------
// Scratch: one big __device__ global (allocation-free rule). 41,943,040 floats
// = 160 MiB.
//  xn1 : [8192,512]
//  q,k,v : [B,H,S,64] each
//  x1  : [8192,512]  (residual + attn out)
//  xn2 : [8192,512]
//  mid : [8192,2048]
// ---------------------------------------------------------------------------
__device__ float g_scratch[41943040];

#define OFF_XN1 0u
#define OFF_Q   4194304u
#define OFF_K   8388608u
#define OFF_V   12582912u
#define OFF_X1  16777216u
#define OFF_XN2 20971520u
#define OFF_MID 25165824u

// ---------------------------------------------------------------------------
// LayerNorm: one block per row, 256 threads, 2 elems/thread (D=512).
// Two-pass (mean, then var) to match jnp.mean((x-mu)^2) closely.
// ---------------------------------------------------------------------------
__global__ __launch_bounds__(256) void ln_kernel(
    const float* __restrict__ x, const float* __restrict__ g,
    const float* __restrict__ b, float* __restrict__ y)
{
    int row = blockIdx.x;
    int t = threadIdx.x;
    const float2* xr = (const float2*)(x + (size_t)row * D_MODEL);
    float2* yr = (float2*)(y + (size_t)row * D_MODEL);
    float2 v = xr[t];

    __shared__ float red[8];

    float s = v.x + v.y;
    #pragma unroll
    for (int o = 16; o > 0; o >>= 1) s += __shfl_xor_sync(0xffffffffu, s, o);
    if ((t & 31) == 0) red[t >> 5] = s;
    __syncthreads();
    float tot = 0.f;
    #pragma unroll
    for (int i = 0; i < 8; i++) tot += red[i];
    float mu = tot * (1.0f / D_MODEL);
    __syncthreads();

    float d0 = v.x - mu, d1 = v.y - mu;
    s = d0 * d0 + d1 * d1;
    #pragma unroll
    for (int o = 16; o > 0; o >>= 1) s += __shfl_xor_sync(0xffffffffu, s, o);
    if ((t & 31) == 0) red[t >> 5] = s;
    __syncthreads();
    tot = 0.f;
    #pragma unroll
    for (int i = 0; i < 8; i++) tot += red[i];
    float inv = rsqrtf(tot * (1.0f / D_MODEL) + 1e-5f);

    float2 gg = ((const float2*)g)[t];
    float2 bb = ((const float2*)b)[t];
    float2 o2;
    o2.x = d0 * inv * gg.x + bb.x;
    o2.y = d1 * inv * gg.y + bb.y;
    yr[t] = o2;
}

// ---------------------------------------------------------------------------
// Generic 128x128x16 register-tiled SGEMM: C = A[8192,K] @ W[K,M] (+epilogue).
// 256 threads, 8x8 per thread. All dims divide tiles exactly (no guards).
// mode 0: scatter to [B,H,S,Dh] with +bias           (QKV projection)
// mode 1: C[row*M+col] = relu(acc + bias)            (FFN layer 1)
// mode 2: C[row*M+col] = acc + bias + resid          (FFN layer 2 + residual)
// ---------------------------------------------------------------------------
__global__ __launch_bounds__(256) void gemm_kernel(
    const float* __restrict__ A, const float* __restrict__ W,
    const float* __restrict__ bias, const float* __restrict__ resid,
    float* __restrict__ C, int K, int M, int mode)
{
    __shared__ float As[16][132];   // [k][m], padded
    __shared__ float Bs[16][128];   // [k][n]

    int tid = threadIdx.x;
    int tx = tid & 15, ty = tid >> 4;
    int rowBase = blockIdx.y * 128;
    int colBase = blockIdx.x * 128;

    float acc[8][8];
    #pragma unroll
    for (int i = 0; i < 8; i++)
        #pragma unroll
        for (int j = 0; j < 8; j++) acc[i][j] = 0.f;

    for (int k0 = 0; k0 < K; k0 += 16) {
        // A tile: 128 rows x 16 cols = 512 float4, 2 per thread, store transposed
        #pragma unroll
        for (int j = 0; j < 2; j++) {
            int i = tid + 256 * j;
            int r = i >> 2, c4 = i & 3;
            float4 f = *(const float4*)(A + (size_t)(rowBase + r) * K + k0 + c4 * 4);
            As[c4 * 4 + 0][r] = f.x;
            As[c4 * 4 + 1][r] = f.y;
            As[c4 * 4 + 2][r] = f.z;
            As[c4 * 4 + 3][r] = f.w;
        }
        // B tile: 16 rows x 128 cols = 512 float4, natural layout
        #pragma unroll
        for (int j = 0; j < 2; j++) {
            int i = tid + 256 * j;
            int r = i >> 5, c4 = i & 31;
            *(float4*)&Bs[r][c4 * 4] =
                *(const float4*)(W + (size_t)(k0 + r) * M + colBase + c4 * 4);
        }
        __syncthreads();

        #pragma unroll
        for (int k = 0; k < 16; k++) {
            float a[8], bb[8];
            *(float4*)&a[0] = *(const float4*)&As[k][ty * 8];
            *(float4*)&a[4] = *(const float4*)&As[k][ty * 8 + 4];
            *(float4*)&bb[0] = *(const float4*)&Bs[k][tx * 8];
            *(float4*)&bb[4] = *(const float4*)&Bs[k][tx * 8 + 4];
            #pragma unroll
            for (int i = 0; i < 8; i++)
                #pragma unroll
                for (int j = 0; j < 8; j++)
                    acc[i][j] = fmaf(a[i], bb[j], acc[i][j]);
        }
        __syncthreads();
    }

    #pragma unroll
    for (int i = 0; i < 8; i++) {
        int row = rowBase + ty * 8 + i;
        #pragma unroll
        for (int j = 0; j < 8; j++) {
            int col = colBase + tx * 8 + j;
            float val = acc[i][j] + bias[col];
            if (mode == 0) {
                int b_ = row >> 11, s = row & 2047, h = col >> 6, d = col & 63;
                C[(((size_t)b_ * N_HEADS + h) * SEQ + s) * DH + d] = val;
            } else if (mode == 1) {
                C[(size_t)row * M + col] = fmaxf(val, 0.f);
            } else {
                C[(size_t)row * M + col] = val + resid[(size_t)row * M + col];
            }
        }
    }
}

// ---------------------------------------------------------------------------
// Sigmoid-pointwise attention, flash-style (no softmax state needed):
//   out[r,:] = sum_t sigmoid(q[r]·k[t] / sqrt(512)) * v[t,:]
// Block = (b, h, 128 q-rows). Loop over 64-row K/V tiles.
// Dynamic smem: Qs[64][132] (k-major) + Ks[64][68] (k-major) + Vs[64][68]
//               + Ps[64][132] (t-major)  = 102400 B.
// Epilogue writes residual: x1 = x + attn_out (per-head column slice).
// ---------------------------------------------------------------------------
#define QSP 132
#define KSP 68

__global__ __launch_bounds__(256, 2) void attn_kernel(
    const float* __restrict__ q, const float* __restrict__ kk,
    const float* __restrict__ vv, const float* __restrict__ x,
    float* __restrict__ x1)
{
    extern __shared__ float sm[];
    float* Qs = sm;                   // [64][QSP]  Qs[d][r]
    float* Ks = Qs + 64 * QSP;        // [64][KSP]  Ks[d][t]
    float* Vs = Ks + 64 * KSP;        // [64][KSP]  Vs[t][d]
    float* Ps = Vs + 64 * KSP;        // [64][QSP]  Ps[t][r]

    int b = blockIdx.z, h = blockIdx.y;
    int s0 = blockIdx.x * 128;
    const float* qbase = q + (((size_t)b * N_HEADS + h) * SEQ + s0) * DH;
    const float* kbase = kk + ((size_t)b * N_HEADS + h) * SEQ * DH;
    const float* vbase = vv + ((size_t)b * N_HEADS + h) * SEQ * DH;

    int tid = threadIdx.x, tx = tid & 15, ty = tid >> 4;

    // Load Q tile transposed (once): 128 rows x 64 d = 2048 float4
    for (int i = tid; i < 128 * 16; i += 256) {
        int r = i >> 4, d4 = i & 15;
        float4 f = *(const float4*)(qbase + (size_t)r * DH + d4 * 4);
        Qs[(d4 * 4 + 0) * QSP + r] = f.x;
        Qs[(d4 * 4 + 1) * QSP + r] = f.y;
        Qs[(d4 * 4 + 2) * QSP + r] = f.z;
        Qs[(d4 * 4 + 3) * QSP + r] = f.w;
    }

    float o[8][4];
    #pragma unroll
    for (int i = 0; i < 8; i++)
        #pragma unroll
        for (int j = 0; j < 4; j++) o[i][j] = 0.f;

    const float scale = 0.04419417382415922f;  // 1/sqrt(512)

    for (int t0 = 0; t0 < SEQ; t0 += 64) {
        __syncthreads();   // protect Ks/Vs/Ps from previous iteration's readers
        // Load K transposed + V natural: 64 rows x 16 float4 each
        for (int i = tid; i < 64 * 16; i += 256) {
            int r = i >> 4, d4 = i & 15;
            float4 f = *(const float4*)(kbase + (size_t)(t0 + r) * DH + d4 * 4);
            Ks[(d4 * 4 + 0) * KSP + r] = f.x;
            Ks[(d4 * 4 + 1) * KSP + r] = f.y;
            Ks[(d4 * 4 + 2) * KSP + r] = f.z;
            Ks[(d4 * 4 + 3) * KSP + r] = f.w;
            float4 g = *(const float4*)(vbase + (size_t)(t0 + r) * DH + d4 * 4);
            *(float4*)&Vs[r * KSP + d4 * 4] = g;
        }
        __syncthreads();

        // mm1: P[r][t] = Q·K^T   (r = ty*8+i, t = tx*4+j)
        float p[8][4];
        #pragma unroll
        for (int i = 0; i < 8; i++)
            #pragma unroll
            for (int j = 0; j < 4; j++) p[i][j] = 0.f;

        #pragma unroll 8
        for (int d = 0; d < 64; d++) {
            float a[8], c[4];
            *(float4*)&a[0] = *(const float4*)&Qs[d * QSP + ty * 8];
            *(float4*)&a[4] = *(const float4*)&Qs[d * QSP + ty * 8 + 4];
            *(float4*)&c[0] = *(const float4*)&Ks[d * KSP + tx * 4];
            #pragma unroll
            for (int i = 0; i < 8; i++)
                #pragma unroll
                for (int j = 0; j < 4; j++)
                    p[i][j] = fmaf(a[i], c[j], p[i][j]);
        }

        // sigmoid + store Ps (t-major)
        #pragma unroll
        for (int i = 0; i < 8; i++)
            #pragma unroll
            for (int j = 0; j < 4; j++) {
                float z = p[i][j] * scale;
                Ps[(tx * 4 + j) * QSP + ty * 8 + i] = 1.0f / (1.0f + expf(-z));
            }
        __syncthreads();

        // mm2: o[r][d] += P[r][t] * V[t][d]   (r = ty*8+i, d = tx*4+j)
        #pragma unroll 8
        for (int t = 0; t < 64; t++) {
            float a[8], c[4];
            *(float4*)&a[0] = *(const float4*)&Ps[t * QSP + ty * 8];
            *(float4*)&a[4] = *(const float4*)&Ps[t * QSP + ty * 8 + 4];
            *(float4*)&c[0] = *(const float4*)&Vs[t * KSP + tx * 4];
            #pragma unroll
            for (int i = 0; i < 8; i++)
                #pragma unroll
                for (int j = 0; j < 4; j++)
                    o[i][j] = fmaf(a[i], c[j], o[i][j]);
        }
    }

    // Epilogue: x1 = x + attn_out (this block owns head-h column slice)
    #pragma unroll
    for (int i = 0; i < 8; i++) {
        int s = s0 + ty * 8 + i;
        #pragma unroll
        for (int j = 0; j < 4; j++) {
            int col = h * DH + tx * 4 + j;
            size_t idx = ((size_t)(b * SEQ + s)) * D_MODEL + col;
            x1[idx] = x[idx] + o[i][j];
        }
    }
}

// ---------------------------------------------------------------------------
// kernel_launch: 8 graph-capturable launches on the default stream.
// Inputs (metadata order): x, Wq, bq, Wk, bk, Wv, bv, W1, b1, W2, b2,
//                          g1, be1, g2, be2
// ---------------------------------------------------------------------------
extern "C" void kernel_launch(void* const* d_in, const int* in_sizes, int n_in,
                              void* d_out, int out_size)
{
    (void)in_sizes; (void)n_in; (void)out_size;
    const float* x   = (const float*)d_in[0];
    const float* Wq  = (const float*)d_in[1];
    const float* bq  = (const float*)d_in[2];
    const float* Wk  = (const float*)d_in[3];
    const float* bk  = (const float*)d_in[4];
    const float* Wv  = (const float*)d_in[5];
    const float* bv  = (const float*)d_in[6];
    const float* W1  = (const float*)d_in[7];
    const float* b1  = (const float*)d_in[8];
    const float* W2  = (const float*)d_in[9];
    const float* b2  = (const float*)d_in[10];
    const float* g1  = (const float*)d_in[11];
    const float* be1 = (const float*)d_in[12];
    const float* g2  = (const float*)d_in[13];
    const float* be2 = (const float*)d_in[14];
    float* out = (float*)d_out;

    float* scratch = nullptr;
    cudaGetSymbolAddress((void**)&scratch, g_scratch);
    float* xn1 = scratch + OFF_XN1;
    float* qb  = scratch + OFF_Q;
    float* kb  = scratch + OFF_K;
    float* vb  = scratch + OFF_V;
    float* x1  = scratch + OFF_X1;
    float* xn2 = scratch + OFF_XN2;
    float* mid = scratch + OFF_MID;

    cudaFuncSetAttribute(attn_kernel,
                         cudaFuncAttributeMaxDynamicSharedMemorySize, 102400);

    // LN1
    ln_kernel<<<NROWS, 256>>>(x, g1, be1, xn1);
    // QKV projections (scatter to [B,H,S,Dh])
    gemm_kernel<<<dim3(4, 64), 256>>>(xn1, Wq, bq, nullptr, qb, 512, 512, 0);
    gemm_kernel<<<dim3(4, 64), 256>>>(xn1, Wk, bk, nullptr, kb, 512, 512, 0);
    gemm_kernel<<<dim3(4, 64), 256>>>(xn1, Wv, bv, nullptr, vb, 512, 512, 0);
    // Sigmoid attention + residual -> x1
    attn_kernel<<<dim3(16, 8, 4), 256, 102400>>>(qb, kb, vb, x, x1);
    // LN2
    ln_kernel<<<NROWS, 256>>>(x1, g2, be2, xn2);
    // FFN
    gemm_kernel<<<dim3(16, 64), 256>>>(xn2, W1, b1, nullptr, mid, 512, 2048, 1);
    gemm_kernel<<<dim3(4, 64), 256>>>(mid, W2, b2, x1, out, 2048, 512, 2);
}

// round 3
// speedup vs baseline: 3.3355x; 3.3355x over previous
#include <cuda_runtime.h>
#include <math.h>
#include <stdint.h>

// Problem constants
#define D_MODEL 512
#define N_HEADS 8
#define DH      64
#define D_FF    2048
#define BATCH   4
#define SEQ     2048
#define NROWS   (BATCH*SEQ)   // 8192

// ---------------------------------------------------------------------------
// Scratch (allocation-free rule): one big __device__ global, 256B aligned.
// ---------------------------------------------------------------------------
__device__ __align__(256) float g_scratch[44826624];

#define OFF_XN1 0u
#define OFF_Q   4194304u
#define OFF_K   8388608u
#define OFF_V   12582912u
#define OFF_X1  16777216u
#define OFF_XN2 20971520u
#define OFF_MID 25165824u
#define OFF_WQ  41943040u
#define OFF_WK  42205184u
#define OFF_WV  42467328u
#define OFF_W1  42729472u
#define OFF_W2  43778048u

// ---------------------------------------------------------------------------
// Helpers
// ---------------------------------------------------------------------------
__device__ __forceinline__ float tf32r(float x) {
    uint32_t u;
    asm("cvt.rna.tf32.f32 %0, %1;" : "=r"(u) : "f"(x));
    return __uint_as_float(u);
}

__device__ __forceinline__ void mma_tf32(float* d, const float* a, const float* b) {
    asm volatile(
        "mma.sync.aligned.m16n8k8.row.col.f32.tf32.tf32.f32 "
        "{%0,%1,%2,%3}, {%4,%5,%6,%7}, {%8,%9}, {%0,%1,%2,%3};\n"
        : "+f"(d[0]), "+f"(d[1]), "+f"(d[2]), "+f"(d[3])
        : "r"(__float_as_uint(a[0])), "r"(__float_as_uint(a[1])),
          "r"(__float_as_uint(a[2])), "r"(__float_as_uint(a[3])),
          "r"(__float_as_uint(b[0])), "r"(__float_as_uint(b[1])));
}

__device__ __forceinline__ void cpasync16(uint32_t s, const float* g) {
    asm volatile("cp.async.cg.shared.global [%0], [%1], 16;" :: "r"(s), "l"(g));
}
__device__ __forceinline__ void cpcommit() { asm volatile("cp.async.commit_group;"); }
__device__ __forceinline__ void cpwait0()  { asm volatile("cp.async.wait_group 0;"); }

// ---------------------------------------------------------------------------
// Round a tensor to tf32 (RNA), vectorized float4.
// ---------------------------------------------------------------------------
__global__ __launch_bounds__(256) void round_tf32_kernel(
    const float4* __restrict__ in, float4* __restrict__ out, int n4)
{
    int i = blockIdx.x * 256 + threadIdx.x;
    if (i < n4) {
        float4 f = in[i];
        f.x = tf32r(f.x); f.y = tf32r(f.y); f.z = tf32r(f.z); f.w = tf32r(f.w);
        out[i] = f;
    }
}

// ---------------------------------------------------------------------------
// LayerNorm: one block per row, 256 threads, output rounded to tf32.
// ---------------------------------------------------------------------------
__global__ __launch_bounds__(256) void ln_kernel(
    const float* __restrict__ x, const float* __restrict__ g,
    const float* __restrict__ b, float* __restrict__ y)
{
    int row = blockIdx.x;
    int t = threadIdx.x;
    const float2* xr = (const float2*)(x + (size_t)row * D_MODEL);
    float2* yr = (float2*)(y + (size_t)row * D_MODEL);
    float2 v = xr[t];

    __shared__ float red[8];

    float s = v.x + v.y;
    #pragma unroll
    for (int o = 16; o > 0; o >>= 1) s += __shfl_xor_sync(0xffffffffu, s, o);
    if ((t & 31) == 0) red[t >> 5] = s;
    __syncthreads();
    float tot = 0.f;
    #pragma unroll
    for (int i = 0; i < 8; i++) tot += red[i];
    float mu = tot * (1.0f / D_MODEL);
    __syncthreads();

    float d0 = v.x - mu, d1 = v.y - mu;
    s = d0 * d0 + d1 * d1;
    #pragma unroll
    for (int o = 16; o > 0; o >>= 1) s += __shfl_xor_sync(0xffffffffu, s, o);
    if ((t & 31) == 0) red[t >> 5] = s;
    __syncthreads();
    tot = 0.f;
    #pragma unroll
    for (int i = 0; i < 8; i++) tot += red[i];
    float inv = rsqrtf(tot * (1.0f / D_MODEL) + 1e-5f);

    float2 gg = ((const float2*)g)[t];
    float2 bb = ((const float2*)b)[t];
    float2 o2;
    o2.x = tf32r(d0 * inv * gg.x + bb.x);
    o2.y = tf32r(d1 * inv * gg.y + bb.y);
    yr[t] = o2;
}

// ---------------------------------------------------------------------------
// TF32 tensor-core GEMM: C = A[8192,K] @ W[K,M] (+epilogue).
// 128x128x32 block tile, 256 threads (8 warps, 2x4), 64x32 warp tiles,
// m16n8k8 mma, cp.async double-buffered smem.
// Smem strides: SA=36 (≡4 mod 32), SB=136 (≡8 mod 32) -> conflict-free gathers.
// mode 0: scatter tf32(acc+bias) to [B,H,S,Dh]     (QKV)
// mode 1: tf32(relu(acc+bias))                     (FFN layer 1)
// mode 2: acc + bias + resid (fp32)                (FFN layer 2 + residual)
// ---------------------------------------------------------------------------
#define SA 36
#define SB 136
#define GEMM_SMEM ((2*128*SA + 2*32*SB) * 4)

__global__ __launch_bounds__(256, 2) void gemm_tc(
    const float* __restrict__ A, const float* __restrict__ W,
    const float* __restrict__ bias, const float* __restrict__ resid,
    float* __restrict__ C, int K, int M, int mode)
{
    extern __shared__ float sm[];
    float* As = sm;                // [2][128][SA]
    float* Bs = sm + 2 * 128 * SA; // [2][32][SB]

    int tid = threadIdx.x;
    int w = tid >> 5, lane = tid & 31;
    int g = lane >> 2, t4 = lane & 3;
    int wr = w >> 2, wc = w & 3;
    int rowBase = blockIdx.y * 128;
    int colBase = blockIdx.x * 128;

    uint32_t sA = (uint32_t)__cvta_generic_to_shared(As);
    uint32_t sB = (uint32_t)__cvta_generic_to_shared(Bs);

    float acc[4][4][4];
    #pragma unroll
    for (int mf = 0; mf < 4; mf++)
        #pragma unroll
        for (int nf = 0; nf < 4; nf++)
            #pragma unroll
            for (int r = 0; r < 4; r++) acc[mf][nf][r] = 0.f;

    // staging indices (4 float4 per thread for A and for B)
    int ar[4], ac[4], br_[4], bc[4];
    #pragma unroll
    for (int j = 0; j < 4; j++) {
        int i = tid + 256 * j;
        ar[j] = i >> 3;  ac[j] = (i & 7) * 4;     // A: 128 rows x 8 float4
        br_[j] = i >> 5; bc[j] = (i & 31) * 4;    // B: 32 rows x 32 float4
    }

    int nk = K >> 5;

    // prefetch tile 0
    #pragma unroll
    for (int j = 0; j < 4; j++) {
        cpasync16(sA + (ar[j] * SA + ac[j]) * 4,
                  A + (size_t)(rowBase + ar[j]) * K + ac[j]);
        cpasync16(sB + (br_[j] * SB + bc[j]) * 4,
                  W + (size_t)br_[j] * M + colBase + bc[j]);
    }
    cpcommit();

    for (int it = 0; it < nk; it++) {
        cpwait0();
        __syncthreads();
        if (it + 1 < nk) {
            int k0 = (it + 1) << 5;
            int buf = (it + 1) & 1;
            #pragma unroll
            for (int j = 0; j < 4; j++) {
                cpasync16(sA + (buf * 128 * SA + ar[j] * SA + ac[j]) * 4,
                          A + (size_t)(rowBase + ar[j]) * K + k0 + ac[j]);
                cpasync16(sB + (buf * 32 * SB + br_[j] * SB + bc[j]) * 4,
                          W + (size_t)(k0 + br_[j]) * M + colBase + bc[j]);
            }
            cpcommit();
        }
        const float* Ab = As + (it & 1) * 128 * SA;
        const float* Bb = Bs + (it & 1) * 32 * SB;

        #pragma unroll
        for (int k8 = 0; k8 < 32; k8 += 8) {
            float a[4][4], bf[4][2];
            #pragma unroll
            for (int mf = 0; mf < 4; mf++) {
                int r0 = wr * 64 + mf * 16 + g;
                a[mf][0] = Ab[r0 * SA + k8 + t4];
                a[mf][1] = Ab[(r0 + 8) * SA + k8 + t4];
                a[mf][2] = Ab[r0 * SA + k8 + t4 + 4];
                a[mf][3] = Ab[(r0 + 8) * SA + k8 + t4 + 4];
            }
            #pragma unroll
            for (int nf = 0; nf < 4; nf++) {
                int c0 = wc * 32 + nf * 8 + g;
                bf[nf][0] = Bb[(k8 + t4) * SB + c0];
                bf[nf][1] = Bb[(k8 + t4 + 4) * SB + c0];
            }
            #pragma unroll
            for (int mf = 0; mf < 4; mf++)
                #pragma unroll
                for (int nf = 0; nf < 4; nf++)
                    mma_tf32(acc[mf][nf], a[mf], bf[nf]);
        }
    }

    // Epilogue
    #pragma unroll
    for (int mf = 0; mf < 4; mf++) {
        int r0 = rowBase + wr * 64 + mf * 16 + g;
        #pragma unroll
        for (int nf = 0; nf < 4; nf++) {
            int c0 = colBase + wc * 32 + nf * 8 + 2 * t4;
            float b0 = bias[c0], b1 = bias[c0 + 1];
            #pragma unroll
            for (int half = 0; half < 2; half++) {
                int row = r0 + half * 8;
                float v0 = acc[mf][nf][half * 2 + 0] + b0;
                float v1 = acc[mf][nf][half * 2 + 1] + b1;
                if (mode == 0) {
                    int b_ = row >> 11, s = row & 2047, h = c0 >> 6, d = c0 & 63;
                    float2 o2 = make_float2(tf32r(v0), tf32r(v1));
                    *(float2*)(C + ((((size_t)b_ * N_HEADS + h) * SEQ + s) * DH + d)) = o2;
                } else if (mode == 1) {
                    float2 o2 = make_float2(tf32r(fmaxf(v0, 0.f)), tf32r(fmaxf(v1, 0.f)));
                    *(float2*)(C + (size_t)row * M + c0) = o2;
                } else {
                    float2 rr = *(const float2*)(resid + (size_t)row * M + c0);
                    float2 o2 = make_float2(v0 + rr.x, v1 + rr.y);
                    *(float2*)(C + (size_t)row * M + c0) = o2;
                }
            }
        }
    }
}

// ---------------------------------------------------------------------------
// Sigmoid-pointwise attention on tensor cores.
// Block = (b, h, 128 q-rows), 512 threads (16 warps). K/V tiles of 128 t.
// mm1: P[128,128] = Q K^T (4x4 warp grid, 32x32 warp tiles)
// sigmoid + tf32 round -> Ps; mm2: O += P V (8x2 warp grid, 16x32 tiles).
// Smem: Qs[128][68] Ks[128][68] Vs[128][72] Ps[128][132] = 174080 B.
// Epilogue: x1 = x + O (per-head column slice).
// ---------------------------------------------------------------------------
#define ASQ 68
#define ASK 68
#define ASV 72
#define ASP 132
#define ATTN_SMEM ((128*ASQ + 128*ASK + 128*ASV + 128*ASP) * 4)

__global__ __launch_bounds__(512, 1) void attn_tc(
    const float* __restrict__ q, const float* __restrict__ kk,
    const float* __restrict__ vv, const float* __restrict__ x,
    float* __restrict__ x1)
{
    extern __shared__ float sm[];
    float* Qs = sm;
    float* Ks = Qs + 128 * ASQ;
    float* Vs = Ks + 128 * ASK;
    float* Ps = Vs + 128 * ASV;

    int b = blockIdx.z, h = blockIdx.y;
    int s0 = blockIdx.x * 128;
    const float* qbase = q + (((size_t)b * N_HEADS + h) * SEQ + s0) * DH;
    const float* kbase = kk + ((size_t)b * N_HEADS + h) * SEQ * DH;
    const float* vbase = vv + ((size_t)b * N_HEADS + h) * SEQ * DH;

    int tid = threadIdx.x, w = tid >> 5, lane = tid & 31;
    int g = lane >> 2, t4 = lane & 3;
    int wr1 = w >> 2, wc1 = w & 3;   // mm1: 4x4 grid of 32x32
    int wr2 = w >> 1, wc2 = w & 1;   // mm2: 8x2 grid of 16x32

    // Load Q (once): 128x64 = 2048 float4
    for (int i = tid; i < 2048; i += 512) {
        int r = i >> 4, c = (i & 15) * 4;
        *(float4*)(Qs + r * ASQ + c) = *(const float4*)(qbase + (size_t)r * DH + c);
    }

    float o[4][4];
    #pragma unroll
    for (int nf = 0; nf < 4; nf++)
        #pragma unroll
        for (int r = 0; r < 4; r++) o[nf][r] = 0.f;

    const float scale = 0.04419417382415922f;  // 1/sqrt(512)

    for (int t0 = 0; t0 < SEQ; t0 += 128) {
        __syncthreads();  // everyone done with prior Ks/Vs/Ps
        for (int i = tid; i < 2048; i += 512) {
            int r = i >> 4, c = (i & 15) * 4;
            *(float4*)(Ks + r * ASK + c) = *(const float4*)(kbase + (size_t)(t0 + r) * DH + c);
            *(float4*)(Vs + r * ASV + c) = *(const float4*)(vbase + (size_t)(t0 + r) * DH + c);
        }
        __syncthreads();

        // mm1: P = Q K^T
        float p[2][4][4];
        #pragma unroll
        for (int mf = 0; mf < 2; mf++)
            #pragma unroll
            for (int nf = 0; nf < 4; nf++)
                #pragma unroll
                for (int r = 0; r < 4; r++) p[mf][nf][r] = 0.f;

        #pragma unroll
        for (int k8 = 0; k8 < 64; k8 += 8) {
            float a[2][4], bf[4][2];
            #pragma unroll
            for (int mf = 0; mf < 2; mf++) {
                int r0 = wr1 * 32 + mf * 16 + g;
                a[mf][0] = Qs[r0 * ASQ + k8 + t4];
                a[mf][1] = Qs[(r0 + 8) * ASQ + k8 + t4];
                a[mf][2] = Qs[r0 * ASQ + k8 + t4 + 4];
                a[mf][3] = Qs[(r0 + 8) * ASQ + k8 + t4 + 4];
            }
            #pragma unroll
            for (int nf = 0; nf < 4; nf++) {
                int tcol = wc1 * 32 + nf * 8 + g;
                bf[nf][0] = Ks[tcol * ASK + k8 + t4];      // B[d][t] = K[t][d]
                bf[nf][1] = Ks[tcol * ASK + k8 + t4 + 4];
            }
            #pragma unroll
            for (int mf = 0; mf < 2; mf++)
                #pragma unroll
                for (int nf = 0; nf < 4; nf++)
                    mma_tf32(p[mf][nf], a[mf], bf[nf]);
        }

        // sigmoid + tf32 round -> Ps
        #pragma unroll
        for (int mf = 0; mf < 2; mf++) {
            int r0 = wr1 * 32 + mf * 16 + g;
            #pragma unroll
            for (int nf = 0; nf < 4; nf++) {
                int c0 = wc1 * 32 + nf * 8 + 2 * t4;
                #pragma unroll
                for (int half = 0; half < 2; half++) {
                    int rr = r0 + half * 8;
                    float z0 = p[mf][nf][half * 2 + 0] * scale;
                    float z1 = p[mf][nf][half * 2 + 1] * scale;
                    Ps[rr * ASP + c0]     = tf32r(__fdividef(1.0f, 1.0f + __expf(-z0)));
                    Ps[rr * ASP + c0 + 1] = tf32r(__fdividef(1.0f, 1.0f + __expf(-z1)));
                }
            }
        }
        __syncthreads();

        // mm2: O += P V
        #pragma unroll 4
        for (int k8 = 0; k8 < 128; k8 += 8) {
            float a[4], bf[4][2];
            int r0 = wr2 * 16 + g;
            a[0] = Ps[r0 * ASP + k8 + t4];
            a[1] = Ps[(r0 + 8) * ASP + k8 + t4];
            a[2] = Ps[r0 * ASP + k8 + t4 + 4];
            a[3] = Ps[(r0 + 8) * ASP + k8 + t4 + 4];
            #pragma unroll
            for (int nf = 0; nf < 4; nf++) {
                int d0 = wc2 * 32 + nf * 8 + g;
                bf[nf][0] = Vs[(k8 + t4) * ASV + d0];
                bf[nf][1] = Vs[(k8 + t4 + 4) * ASV + d0];
            }
            #pragma unroll
            for (int nf = 0; nf < 4; nf++)
                mma_tf32(o[nf], a, bf[nf]);
        }
    }

    // Epilogue: x1 = x + O
    int r0 = wr2 * 16 + g;
    #pragma unroll
    for (int nf = 0; nf < 4; nf++) {
        int col = h * DH + wc2 * 32 + nf * 8 + 2 * t4;
        #pragma unroll
        for (int half = 0; half < 2; half++) {
            int s = s0 + r0 + half * 8;
            size_t idx = ((size_t)(b * SEQ + s)) * D_MODEL + col;
            float2 xr = *(const float2*)(x + idx);
            float2 o2 = make_float2(xr.x + o[nf][half * 2 + 0],
                                    xr.y + o[nf][half * 2 + 1]);
            *(float2*)(x1 + idx) = o2;
        }
    }
}

// ---------------------------------------------------------------------------
// kernel_launch
// ---------------------------------------------------------------------------
extern "C" void kernel_launch(void* const* d_in, const int* in_sizes, int n_in,
                              void* d_out, int out_size)
{
    (void)in_sizes; (void)n_in; (void)out_size;
    const float* x   = (const float*)d_in[0];
    const float* Wq  = (const float*)d_in[1];
    const float* bq  = (const float*)d_in[2];
    const float* Wk  = (const float*)d_in[3];
    const float* bk  = (const float*)d_in[4];
    const float* Wv  = (const float*)d_in[5];
    const float* bv  = (const float*)d_in[6];
    const float* W1  = (const float*)d_in[7];
    const float* b1  = (const float*)d_in[8];
    const float* W2  = (const float*)d_in[9];
    const float* b2  = (const float*)d_in[10];
    const float* g1  = (const float*)d_in[11];
    const float* be1 = (const float*)d_in[12];
    const float* g2  = (const float*)d_in[13];
    const float* be2 = (const float*)d_in[14];
    float* out = (float*)d_out;

    float* scratch = nullptr;
    cudaGetSymbolAddress((void**)&scratch, g_scratch);
    float* xn1 = scratch + OFF_XN1;
    float* qb  = scratch + OFF_Q;
    float* kb  = scratch + OFF_K;
    float* vb  = scratch + OFF_V;
    float* x1  = scratch + OFF_X1;
    float* xn2 = scratch + OFF_XN2;
    float* mid = scratch + OFF_MID;
    float* wq_r = scratch + OFF_WQ;
    float* wk_r = scratch + OFF_WK;
    float* wv_r = scratch + OFF_WV;
    float* w1_r = scratch + OFF_W1;
    float* w2_r = scratch + OFF_W2;

    cudaFuncSetAttribute(gemm_tc, cudaFuncAttributeMaxDynamicSharedMemorySize, GEMM_SMEM);
    cudaFuncSetAttribute(attn_tc, cudaFuncAttributeMaxDynamicSharedMemorySize, ATTN_SMEM);

    // Round weights to tf32 (RNA)
    round_tf32_kernel<<<256, 256>>>((const float4*)Wq, (float4*)wq_r, 65536);
    round_tf32_kernel<<<256, 256>>>((const float4*)Wk, (float4*)wk_r, 65536);
    round_tf32_kernel<<<256, 256>>>((const float4*)Wv, (float4*)wv_r, 65536);
    round_tf32_kernel<<<1024, 256>>>((const float4*)W1, (float4*)w1_r, 262144);
    round_tf32_kernel<<<1024, 256>>>((const float4*)W2, (float4*)w2_r, 262144);

    // LN1 (tf32-rounded output)
    ln_kernel<<<NROWS, 256>>>(x, g1, be1, xn1);
    // QKV projections -> [B,H,S,Dh] (tf32-rounded)
    gemm_tc<<<dim3(4, 64), 256, GEMM_SMEM>>>(xn1, wq_r, bq, nullptr, qb, 512, 512, 0);
    gemm_tc<<<dim3(4, 64), 256, GEMM_SMEM>>>(xn1, wk_r, bk, nullptr, kb, 512, 512, 0);
    gemm_tc<<<dim3(4, 64), 256, GEMM_SMEM>>>(xn1, wv_r, bv, nullptr, vb, 512, 512, 0);
    // Sigmoid attention + residual -> x1
    attn_tc<<<dim3(16, 8, 4), 512, ATTN_SMEM>>>(qb, kb, vb, x, x1);
    // LN2
    ln_kernel<<<NROWS, 256>>>(x1, g2, be2, xn2);
    // FFN
    gemm_tc<<<dim3(16, 64), 256, GEMM_SMEM>>>(xn2, w1_r, b1, nullptr, mid, 512, 2048, 1);
    gemm_tc<<<dim3(4, 64), 256, GEMM_SMEM>>>(mid, w2_r, b2, x1, out, 2048, 512, 2);
}

// round 4
// speedup vs baseline: 4.8975x; 1.4683x over previous
#include <cuda_runtime.h>
#include <cuda_fp16.h>
#include <math.h>
#include <stdint.h>

// Problem constants
#define D_MODEL 512
#define N_HEADS 8
#define DH      64
#define D_FF    2048
#define BATCH   4
#define SEQ     2048
#define NROWS   (BATCH*SEQ)   // 8192

// ---------------------------------------------------------------------------
// Scratch (allocation-free rule). Offsets in floats; half buffers reinterpret.
// ---------------------------------------------------------------------------
__device__ __align__(256) float g_scratch[25165824];

#define OFF_XN1 0u          // half [8192][512]
#define OFF_Q   2097152u    // half [B][H][S][Dh]
#define OFF_K   4194304u    // half [B][H][S][Dh]
#define OFF_V   6291456u    // half [B][H][Dh][S]  (transposed!)
#define OFF_X1  8388608u    // float [8192][512]
#define OFF_XN2 12582912u   // half [8192][512]
#define OFF_MID 14680064u   // half [8192][2048]
#define OFF_WQ  23068672u   // half [512][512]  (transposed [out][in])
#define OFF_WK  23199744u
#define OFF_WV  23330816u
#define OFF_W1  23461888u   // half [2048][512]
#define OFF_W2  23986176u   // half [512][2048]

// ---------------------------------------------------------------------------
// Helpers
// ---------------------------------------------------------------------------
__device__ __forceinline__ void mma_f16(float* d, const uint32_t* a, const uint32_t* b) {
    asm volatile(
        "mma.sync.aligned.m16n8k16.row.col.f32.f16.f16.f32 "
        "{%0,%1,%2,%3}, {%4,%5,%6,%7}, {%8,%9}, {%0,%1,%2,%3};\n"
        : "+f"(d[0]), "+f"(d[1]), "+f"(d[2]), "+f"(d[3])
        : "r"(a[0]), "r"(a[1]), "r"(a[2]), "r"(a[3]), "r"(b[0]), "r"(b[1]));
}

__device__ __forceinline__ uint32_t ldh2(const __half* p) {
    return *(const uint32_t*)p;
}

__device__ __forceinline__ void cpasync16(uint32_t s, const void* g) {
    asm volatile("cp.async.cg.shared.global [%0], [%1], 16;" :: "r"(s), "l"(g));
}
__device__ __forceinline__ void cpcommit() { asm volatile("cp.async.commit_group;"); }
__device__ __forceinline__ void cpwait0()  { asm volatile("cp.async.wait_group 0;"); }

// ---------------------------------------------------------------------------
// Weight convert + transpose: W fp32 [K][M] -> Wt half [M][K].
// Block (32,8), tile 32x32.
// ---------------------------------------------------------------------------
__global__ __launch_bounds__(256) void transpose_half_kernel(
    const float* __restrict__ W, __half* __restrict__ Wt, int K, int M)
{
    __shared__ float t[32][33];
    int m0 = blockIdx.x * 32, k0 = blockIdx.y * 32;
    int tx = threadIdx.x, ty = threadIdx.y;
    #pragma unroll
    for (int j = 0; j < 4; j++) {
        int kr = ty + j * 8;
        t[kr][tx] = W[(size_t)(k0 + kr) * M + m0 + tx];
    }
    __syncthreads();
    #pragma unroll
    for (int j = 0; j < 4; j++) {
        int mr = ty + j * 8;
        Wt[(size_t)(m0 + mr) * K + k0 + tx] = __float2half(t[tx][mr]);
    }
}

// ---------------------------------------------------------------------------
// LayerNorm: block per row, 256 threads, half output.
// ---------------------------------------------------------------------------
__global__ __launch_bounds__(256) void ln_kernel(
    const float* __restrict__ x, const float* __restrict__ g,
    const float* __restrict__ b, __half* __restrict__ y)
{
    int row = blockIdx.x;
    int t = threadIdx.x;
    const float2* xr = (const float2*)(x + (size_t)row * D_MODEL);
    __half2* yr = (__half2*)(y + (size_t)row * D_MODEL);
    float2 v = xr[t];

    __shared__ float red[8];

    float s = v.x + v.y;
    #pragma unroll
    for (int o = 16; o > 0; o >>= 1) s += __shfl_xor_sync(0xffffffffu, s, o);
    if ((t & 31) == 0) red[t >> 5] = s;
    __syncthreads();
    float tot = 0.f;
    #pragma unroll
    for (int i = 0; i < 8; i++) tot += red[i];
    float mu = tot * (1.0f / D_MODEL);
    __syncthreads();

    float d0 = v.x - mu, d1 = v.y - mu;
    s = d0 * d0 + d1 * d1;
    #pragma unroll
    for (int o = 16; o > 0; o >>= 1) s += __shfl_xor_sync(0xffffffffu, s, o);
    if ((t & 31) == 0) red[t >> 5] = s;
    __syncthreads();
    tot = 0.f;
    #pragma unroll
    for (int i = 0; i < 8; i++) tot += red[i];
    float inv = rsqrtf(tot * (1.0f / D_MODEL) + 1e-5f);

    float2 gg = ((const float2*)g)[t];
    float2 bb = ((const float2*)b)[t];
    yr[t] = __floats2half2_rn(d0 * inv * gg.x + bb.x, d1 * inv * gg.y + bb.y);
}

// ---------------------------------------------------------------------------
// FP16 tensor-core GEMM: C = A[8192,K] @ Wt^T  (Wt stored [M][K] half).
// 128x128x32 block tile, 256 threads (8 warps, 2x4), 64x32 warp tiles,
// m16n8k16, cp.async double-buffered. Smem stride 40 halves (20 words ≡ 4 mod 8).
// mode 0: half2(acc+bias) scatter to [B,H,S,Dh]      (Q,K proj)
// mode 3: half (acc+bias) scatter to [B,H,Dh,S]      (V proj, transposed)
// mode 1: half2 relu(acc+bias)  -> C[row*M+col]      (FFN1)
// mode 2: fp32 acc+bias+resid   -> C[row*M+col]      (FFN2 + residual)
// ---------------------------------------------------------------------------
#define SH 40
#define GEMM_SMEM (2*(2*128*SH*2))   // 40960 B

__global__ __launch_bounds__(256, 2) void gemm_h(
    const __half* __restrict__ A, const __half* __restrict__ Wt,
    const float* __restrict__ bias, const float* __restrict__ resid,
    void* __restrict__ Cv, int K, int M, int mode)
{
    extern __shared__ __half sm[];
    __half* As = sm;                 // [2][128][SH]
    __half* Bs = sm + 2 * 128 * SH;  // [2][128][SH]

    int tid = threadIdx.x;
    int w = tid >> 5, lane = tid & 31;
    int g = lane >> 2, t4 = lane & 3;
    int wr = w >> 2, wc = w & 3;
    int rowBase = blockIdx.y * 128;
    int colBase = blockIdx.x * 128;

    uint32_t sA = (uint32_t)__cvta_generic_to_shared(As);
    uint32_t sB = (uint32_t)__cvta_generic_to_shared(Bs);

    float acc[4][4][4];
    #pragma unroll
    for (int mf = 0; mf < 4; mf++)
        #pragma unroll
        for (int nf = 0; nf < 4; nf++)
            #pragma unroll
            for (int r = 0; r < 4; r++) acc[mf][nf][r] = 0.f;

    // staging: tile = 128 rows x 32 halves = 512 x 16B chunks, 2 per thread
    int rr[2], rc[2];
    #pragma unroll
    for (int j = 0; j < 2; j++) {
        int i = tid + 256 * j;
        rr[j] = i >> 2; rc[j] = (i & 3) * 8;
    }

    int nk = K >> 5;

    #pragma unroll
    for (int j = 0; j < 2; j++) {
        cpasync16(sA + (rr[j] * SH + rc[j]) * 2, A + (size_t)(rowBase + rr[j]) * K + rc[j]);
        cpasync16(sB + (rr[j] * SH + rc[j]) * 2, Wt + (size_t)(colBase + rr[j]) * K + rc[j]);
    }
    cpcommit();

    for (int it = 0; it < nk; it++) {
        cpwait0();
        __syncthreads();
        if (it + 1 < nk) {
            int k0 = (it + 1) << 5;
            int buf = (it + 1) & 1;
            #pragma unroll
            for (int j = 0; j < 2; j++) {
                cpasync16(sA + (buf * 128 * SH + rr[j] * SH + rc[j]) * 2,
                          A + (size_t)(rowBase + rr[j]) * K + k0 + rc[j]);
                cpasync16(sB + (buf * 128 * SH + rr[j] * SH + rc[j]) * 2,
                          Wt + (size_t)(colBase + rr[j]) * K + k0 + rc[j]);
            }
            cpcommit();
        }
        const __half* Ab = As + (it & 1) * 128 * SH;
        const __half* Bb = Bs + (it & 1) * 128 * SH;

        #pragma unroll
        for (int ks = 0; ks < 32; ks += 16) {
            uint32_t a[4][4], bf[4][2];
            #pragma unroll
            for (int mf = 0; mf < 4; mf++) {
                int r0 = wr * 64 + mf * 16 + g;
                a[mf][0] = ldh2(Ab + r0 * SH + ks + 2 * t4);
                a[mf][1] = ldh2(Ab + (r0 + 8) * SH + ks + 2 * t4);
                a[mf][2] = ldh2(Ab + r0 * SH + ks + 8 + 2 * t4);
                a[mf][3] = ldh2(Ab + (r0 + 8) * SH + ks + 8 + 2 * t4);
            }
            #pragma unroll
            for (int nf = 0; nf < 4; nf++) {
                int n0 = wc * 32 + nf * 8 + g;
                bf[nf][0] = ldh2(Bb + n0 * SH + ks + 2 * t4);
                bf[nf][1] = ldh2(Bb + n0 * SH + ks + 8 + 2 * t4);
            }
            #pragma unroll
            for (int mf = 0; mf < 4; mf++)
                #pragma unroll
                for (int nf = 0; nf < 4; nf++)
                    mma_f16(acc[mf][nf], a[mf], bf[nf]);
        }
        __syncthreads();
    }

    // Epilogue
    #pragma unroll
    for (int mf = 0; mf < 4; mf++) {
        int r0 = rowBase + wr * 64 + mf * 16 + g;
        #pragma unroll
        for (int nf = 0; nf < 4; nf++) {
            int c0 = colBase + wc * 32 + nf * 8 + 2 * t4;
            float b0 = bias[c0], b1 = bias[c0 + 1];
            #pragma unroll
            for (int half_ = 0; half_ < 2; half_++) {
                int row = r0 + half_ * 8;
                float v0 = acc[mf][nf][half_ * 2 + 0] + b0;
                float v1 = acc[mf][nf][half_ * 2 + 1] + b1;
                if (mode == 0) {
                    int b_ = row >> 11, s = row & 2047, h = c0 >> 6, d = c0 & 63;
                    __half2* C = (__half2*)((__half*)Cv +
                        ((((size_t)b_ * N_HEADS + h) * SEQ + s) * DH + d));
                    *C = __floats2half2_rn(v0, v1);
                } else if (mode == 3) {
                    int b_ = row >> 11, s = row & 2047, h = c0 >> 6, d = c0 & 63;
                    __half* C = (__half*)Cv;
                    size_t base = (((size_t)b_ * N_HEADS + h) * DH + d) * SEQ + s;
                    C[base] = __float2half(v0);
                    C[base + SEQ] = __float2half(v1);
                } else if (mode == 1) {
                    __half2* C = (__half2*)((__half*)Cv + (size_t)row * M + c0);
                    *C = __floats2half2_rn(fmaxf(v0, 0.f), fmaxf(v1, 0.f));
                } else {
                    float2 rv = *(const float2*)(resid + (size_t)row * M + c0);
                    *(float2*)((float*)Cv + (size_t)row * M + c0) =
                        make_float2(v0 + rv.x, v1 + rv.y);
                }
            }
        }
    }
}

// ---------------------------------------------------------------------------
// Sigmoid-pointwise attention, fp16 tensor cores.
// Block = (b, h, 128 q-rows), 512 threads (16 warps). K/V tiles of 128 t.
// mm1: P = Q K^T (4x4 warps, 32x32 tiles); sigmoid -> half Ps;
// mm2: O += P V (8x2 warps, 16x32 tiles). V is stored [d][s] in gmem.
// Smem (halves): Qs[128][72] Ks[128][72] Vs[64][136] Ps[128][136] = 89088 B.
// ---------------------------------------------------------------------------
#define AQ 72
#define AV 136
#define ATTN_SMEM ((128*AQ + 128*AQ + 64*AV + 128*AV) * 2)

__global__ __launch_bounds__(512, 1) void attn_h(
    const __half* __restrict__ q, const __half* __restrict__ kk,
    const __half* __restrict__ vv, const float* __restrict__ x,
    float* __restrict__ x1)
{
    extern __shared__ __half sm[];
    __half* Qs = sm;                 // [128][AQ]  [s][d]
    __half* Ks = Qs + 128 * AQ;      // [128][AQ]  [t][d]
    __half* Vs = Ks + 128 * AQ;      // [64][AV]   [d][t]
    __half* Ps = Vs + 64 * AV;       // [128][AV]  [s][t]

    int b = blockIdx.z, h = blockIdx.y;
    int s0 = blockIdx.x * 128;
    const __half* qbase = q + (((size_t)b * N_HEADS + h) * SEQ + s0) * DH;
    const __half* kbase = kk + ((size_t)b * N_HEADS + h) * SEQ * DH;
    const __half* vbase = vv + ((size_t)b * N_HEADS + h) * DH * SEQ;

    int tid = threadIdx.x, w = tid >> 5, lane = tid & 31;
    int g = lane >> 2, t4 = lane & 3;
    int wr1 = w >> 2, wc1 = w & 3;   // mm1: 4x4 grid of 32x32
    int wr2 = w >> 1, wc2 = w & 1;   // mm2: 8x2 grid of 16x32

    // Load Q once: 128 rows x 64 halves = 1024 x 16B
    for (int i = tid; i < 1024; i += 512) {
        int r = i >> 3, c = (i & 7) * 8;
        *(float4*)(Qs + r * AQ + c) = *(const float4*)(qbase + (size_t)r * DH + c);
    }

    float o[4][4];
    #pragma unroll
    for (int nf = 0; nf < 4; nf++)
        #pragma unroll
        for (int r = 0; r < 4; r++) o[nf][r] = 0.f;

    const float scale = 0.04419417382415922f;  // 1/sqrt(512)

    for (int t0 = 0; t0 < SEQ; t0 += 128) {
        __syncthreads();
        // K tile: 128 t x 64 d halves
        for (int i = tid; i < 1024; i += 512) {
            int r = i >> 3, c = (i & 7) * 8;
            *(float4*)(Ks + r * AQ + c) = *(const float4*)(kbase + (size_t)(t0 + r) * DH + c);
        }
        // V tile: 64 d x 128 t halves
        for (int i = tid; i < 1024; i += 512) {
            int d = i >> 4, c = (i & 15) * 8;
            *(float4*)(Vs + d * AV + c) = *(const float4*)(vbase + (size_t)d * SEQ + t0 + c);
        }
        __syncthreads();

        // mm1: P = Q K^T  (A = Qs[s][d], B = Ks[t][d] as col-major KxN)
        float p[2][4][4];
        #pragma unroll
        for (int mf = 0; mf < 2; mf++)
            #pragma unroll
            for (int nf = 0; nf < 4; nf++)
                #pragma unroll
                for (int r = 0; r < 4; r++) p[mf][nf][r] = 0.f;

        #pragma unroll
        for (int ks = 0; ks < 64; ks += 16) {
            uint32_t a[2][4], bf[4][2];
            #pragma unroll
            for (int mf = 0; mf < 2; mf++) {
                int r0 = wr1 * 32 + mf * 16 + g;
                a[mf][0] = ldh2(Qs + r0 * AQ + ks + 2 * t4);
                a[mf][1] = ldh2(Qs + (r0 + 8) * AQ + ks + 2 * t4);
                a[mf][2] = ldh2(Qs + r0 * AQ + ks + 8 + 2 * t4);
                a[mf][3] = ldh2(Qs + (r0 + 8) * AQ + ks + 8 + 2 * t4);
            }
            #pragma unroll
            for (int nf = 0; nf < 4; nf++) {
                int n0 = wc1 * 32 + nf * 8 + g;
                bf[nf][0] = ldh2(Ks + n0 * AQ + ks + 2 * t4);
                bf[nf][1] = ldh2(Ks + n0 * AQ + ks + 8 + 2 * t4);
            }
            #pragma unroll
            for (int mf = 0; mf < 2; mf++)
                #pragma unroll
                for (int nf = 0; nf < 4; nf++)
                    mma_f16(p[mf][nf], a[mf], bf[nf]);
        }

        // sigmoid -> half Ps[s][t]
        #pragma unroll
        for (int mf = 0; mf < 2; mf++) {
            int r0 = wr1 * 32 + mf * 16 + g;
            #pragma unroll
            for (int nf = 0; nf < 4; nf++) {
                int c0 = wc1 * 32 + nf * 8 + 2 * t4;
                #pragma unroll
                for (int half_ = 0; half_ < 2; half_++) {
                    int rw = r0 + half_ * 8;
                    float z0 = p[mf][nf][half_ * 2 + 0] * scale;
                    float z1 = p[mf][nf][half_ * 2 + 1] * scale;
                    float s0v = __fdividef(1.0f, 1.0f + __expf(-z0));
                    float s1v = __fdividef(1.0f, 1.0f + __expf(-z1));
                    *(__half2*)(Ps + rw * AV + c0) = __floats2half2_rn(s0v, s1v);
                }
            }
        }
        __syncthreads();

        // mm2: O += P V  (A = Ps[s][t], B = Vs[d][t] as col-major KxN)
        #pragma unroll
        for (int ks = 0; ks < 128; ks += 16) {
            uint32_t a[4], bf[4][2];
            int r0 = wr2 * 16 + g;
            a[0] = ldh2(Ps + r0 * AV + ks + 2 * t4);
            a[1] = ldh2(Ps + (r0 + 8) * AV + ks + 2 * t4);
            a[2] = ldh2(Ps + r0 * AV + ks + 8 + 2 * t4);
            a[3] = ldh2(Ps + (r0 + 8) * AV + ks + 8 + 2 * t4);
            #pragma unroll
            for (int nf = 0; nf < 4; nf++) {
                int d0 = wc2 * 32 + nf * 8 + g;
                bf[nf][0] = ldh2(Vs + d0 * AV + ks + 2 * t4);
                bf[nf][1] = ldh2(Vs + d0 * AV + ks + 8 + 2 * t4);
            }
            #pragma unroll
            for (int nf = 0; nf < 4; nf++)
                mma_f16(o[nf], a, bf[nf]);
        }
    }

    // Epilogue: x1 = x + O
    int r0 = wr2 * 16 + g;
    #pragma unroll
    for (int nf = 0; nf < 4; nf++) {
        int col = h * DH + wc2 * 32 + nf * 8 + 2 * t4;
        #pragma unroll
        for (int half_ = 0; half_ < 2; half_++) {
            int s = s0 + r0 + half_ * 8;
            size_t idx = ((size_t)(b * SEQ + s)) * D_MODEL + col;
            float2 xr = *(const float2*)(x + idx);
            *(float2*)(x1 + idx) = make_float2(xr.x + o[nf][half_ * 2 + 0],
                                               xr.y + o[nf][half_ * 2 + 1]);
        }
    }
}

// ---------------------------------------------------------------------------
// kernel_launch
// ---------------------------------------------------------------------------
extern "C" void kernel_launch(void* const* d_in, const int* in_sizes, int n_in,
                              void* d_out, int out_size)
{
    (void)in_sizes; (void)n_in; (void)out_size;
    const float* x   = (const float*)d_in[0];
    const float* Wq  = (const float*)d_in[1];
    const float* bq  = (const float*)d_in[2];
    const float* Wk  = (const float*)d_in[3];
    const float* bk  = (const float*)d_in[4];
    const float* Wv  = (const float*)d_in[5];
    const float* bv  = (const float*)d_in[6];
    const float* W1  = (const float*)d_in[7];
    const float* b1  = (const float*)d_in[8];
    const float* W2  = (const float*)d_in[9];
    const float* b2  = (const float*)d_in[10];
    const float* g1  = (const float*)d_in[11];
    const float* be1 = (const float*)d_in[12];
    const float* g2  = (const float*)d_in[13];
    const float* be2 = (const float*)d_in[14];
    float* out = (float*)d_out;

    float* scratch = nullptr;
    cudaGetSymbolAddress((void**)&scratch, g_scratch);
    __half* xn1 = (__half*)(scratch + OFF_XN1);
    __half* qb  = (__half*)(scratch + OFF_Q);
    __half* kb  = (__half*)(scratch + OFF_K);
    __half* vb  = (__half*)(scratch + OFF_V);
    float*  x1  = scratch + OFF_X1;
    __half* xn2 = (__half*)(scratch + OFF_XN2);
    __half* mid = (__half*)(scratch + OFF_MID);
    __half* wqt = (__half*)(scratch + OFF_WQ);
    __half* wkt = (__half*)(scratch + OFF_WK);
    __half* wvt = (__half*)(scratch + OFF_WV);
    __half* w1t = (__half*)(scratch + OFF_W1);
    __half* w2t = (__half*)(scratch + OFF_W2);

    cudaFuncSetAttribute(gemm_h, cudaFuncAttributeMaxDynamicSharedMemorySize, GEMM_SMEM);
    cudaFuncSetAttribute(attn_h, cudaFuncAttributeMaxDynamicSharedMemorySize, ATTN_SMEM);

    dim3 tb(32, 8);
    // Transpose+convert weights to half [out][in]
    transpose_half_kernel<<<dim3(16, 16), tb>>>(Wq, wqt, 512, 512);
    transpose_half_kernel<<<dim3(16, 16), tb>>>(Wk, wkt, 512, 512);
    transpose_half_kernel<<<dim3(16, 16), tb>>>(Wv, wvt, 512, 512);
    transpose_half_kernel<<<dim3(64, 16), tb>>>(W1, w1t, 512, 2048);
    transpose_half_kernel<<<dim3(16, 64), tb>>>(W2, w2t, 2048, 512);

    // LN1 -> half
    ln_kernel<<<NROWS, 256>>>(x, g1, be1, xn1);
    // QKV projections (Q,K: [B,H,S,Dh]; V: [B,H,Dh,S])
    gemm_h<<<dim3(4, 64), 256, GEMM_SMEM>>>(xn1, wqt, bq, nullptr, qb, 512, 512, 0);
    gemm_h<<<dim3(4, 64), 256, GEMM_SMEM>>>(xn1, wkt, bk, nullptr, kb, 512, 512, 0);
    gemm_h<<<dim3(4, 64), 256, GEMM_SMEM>>>(xn1, wvt, bv, nullptr, vb, 512, 512, 3);
    // Sigmoid attention + residual -> x1 (fp32)
    attn_h<<<dim3(16, 8, 4), 512, ATTN_SMEM>>>(qb, kb, vb, x, x1);
    // LN2 -> half
    ln_kernel<<<NROWS, 256>>>(x1, g2, be2, xn2);
    // FFN
    gemm_h<<<dim3(16, 64), 256, GEMM_SMEM>>>(xn2, w1t, b1, nullptr, mid, 512, 2048, 1);
    gemm_h<<<dim3(4, 64), 256, GEMM_SMEM>>>(mid, w2t, b2, x1, out, 2048, 512, 2);
}

// round 5
// speedup vs baseline: 5.7417x; 1.1724x over previous
#include <cuda_runtime.h>
#include <cuda_fp16.h>
#include <math.h>
#include <stdint.h>

// Problem constants
#define D_MODEL 512
#define N_HEADS 8
#define DH      64
#define D_FF    2048
#define BATCH   4
#define SEQ     2048
#define NROWS   (BATCH*SEQ)   // 8192

// ---------------------------------------------------------------------------
// Scratch (allocation-free rule). Offsets in floats; half buffers reinterpret.
// ---------------------------------------------------------------------------
__device__ __align__(256) float g_scratch[25165824];

#define OFF_XN1  0u          // half [8192][512]
#define OFF_Q    2097152u    // half [B][H][S][Dh]   (K at +2097152, V at +4194304)
#define OFF_K    4194304u    // half [B][H][S][Dh]
#define OFF_V    6291456u    // half [B][H][Dh][S]  (transposed!)
#define OFF_X1   8388608u    // float [8192][512]
#define OFF_XN2  12582912u   // half [8192][512]
#define OFF_MID  14680064u   // half [8192][2048]
#define OFF_WQKV 23068672u   // half [1536][512]  (transposed [out][in], Q|K|V)
#define OFF_W1   23461888u   // half [2048][512]
#define OFF_W2   23986176u   // half [512][2048]
#define OFF_BQKV 24510464u   // float [1536]

// ---------------------------------------------------------------------------
// Helpers
// ---------------------------------------------------------------------------
__device__ __forceinline__ void mma_f16(float* d, const uint32_t* a, const uint32_t* b) {
    asm volatile(
        "mma.sync.aligned.m16n8k16.row.col.f32.f16.f16.f32 "
        "{%0,%1,%2,%3}, {%4,%5,%6,%7}, {%8,%9}, {%0,%1,%2,%3};\n"
        : "+f"(d[0]), "+f"(d[1]), "+f"(d[2]), "+f"(d[3])
        : "r"(a[0]), "r"(a[1]), "r"(a[2]), "r"(a[3]), "r"(b[0]), "r"(b[1]));
}

__device__ __forceinline__ uint32_t ldh2(const __half* p) {
    return *(const uint32_t*)p;
}

__device__ __forceinline__ uint32_t sigmoid_h2(float z0, float z1) {
    // sigmoid(z) = 0.5 + 0.5*tanh(0.5*z); inputs are already 0.5*scale*score
    __half2 hz = __floats2half2_rn(z0, z1);
    uint32_t u = *(uint32_t*)&hz;
    uint32_t t;
    asm("tanh.approx.f16x2 %0, %1;" : "=r"(t) : "r"(u));
    __half2 th = *(__half2*)&t;
    __half2 r = __hfma2(th, __float2half2_rn(0.5f), __float2half2_rn(0.5f));
    return *(uint32_t*)&r;
}

__device__ __forceinline__ void cpasync16(uint32_t s, const void* g) {
    asm volatile("cp.async.cg.shared.global [%0], [%1], 16;" :: "r"(s), "l"(g));
}
__device__ __forceinline__ void cpcommit() { asm volatile("cp.async.commit_group;"); }
__device__ __forceinline__ void cpwait0()  { asm volatile("cp.async.wait_group 0;"); }

// ---------------------------------------------------------------------------
// Weight convert + transpose: W fp32 [K][M] -> Wt half [M][K].
// ---------------------------------------------------------------------------
__global__ __launch_bounds__(256) void transpose_half_kernel(
    const float* __restrict__ W, __half* __restrict__ Wt, int K, int M)
{
    __shared__ float t[32][33];
    int m0 = blockIdx.x * 32, k0 = blockIdx.y * 32;
    int tx = threadIdx.x, ty = threadIdx.y;
    #pragma unroll
    for (int j = 0; j < 4; j++) {
        int kr = ty + j * 8;
        t[kr][tx] = W[(size_t)(k0 + kr) * M + m0 + tx];
    }
    __syncthreads();
    #pragma unroll
    for (int j = 0; j < 4; j++) {
        int mr = ty + j * 8;
        Wt[(size_t)(m0 + mr) * K + k0 + tx] = __float2half(t[tx][mr]);
    }
}

// Concat three 512-float bias vectors.
__global__ __launch_bounds__(512) void concat_bias_kernel(
    const float* __restrict__ a, const float* __restrict__ b,
    const float* __restrict__ c, float* __restrict__ o)
{
    int t = threadIdx.x;
    o[t] = a[t]; o[512 + t] = b[t]; o[1024 + t] = c[t];
}

// ---------------------------------------------------------------------------
// LayerNorm: block per row, 256 threads, half output.
// ---------------------------------------------------------------------------
__global__ __launch_bounds__(256) void ln_kernel(
    const float* __restrict__ x, const float* __restrict__ g,
    const float* __restrict__ b, __half* __restrict__ y)
{
    int row = blockIdx.x;
    int t = threadIdx.x;
    const float2* xr = (const float2*)(x + (size_t)row * D_MODEL);
    __half2* yr = (__half2*)(y + (size_t)row * D_MODEL);
    float2 v = xr[t];

    __shared__ float red[8];

    float s = v.x + v.y;
    #pragma unroll
    for (int o = 16; o > 0; o >>= 1) s += __shfl_xor_sync(0xffffffffu, s, o);
    if ((t & 31) == 0) red[t >> 5] = s;
    __syncthreads();
    float tot = 0.f;
    #pragma unroll
    for (int i = 0; i < 8; i++) tot += red[i];
    float mu = tot * (1.0f / D_MODEL);
    __syncthreads();

    float d0 = v.x - mu, d1 = v.y - mu;
    s = d0 * d0 + d1 * d1;
    #pragma unroll
    for (int o = 16; o > 0; o >>= 1) s += __shfl_xor_sync(0xffffffffu, s, o);
    if ((t & 31) == 0) red[t >> 5] = s;
    __syncthreads();
    tot = 0.f;
    #pragma unroll
    for (int i = 0; i < 8; i++) tot += red[i];
    float inv = rsqrtf(tot * (1.0f / D_MODEL) + 1e-5f);

    float2 gg = ((const float2*)g)[t];
    float2 bb = ((const float2*)b)[t];
    yr[t] = __floats2half2_rn(d0 * inv * gg.x + bb.x, d1 * inv * gg.y + bb.y);
}

// ---------------------------------------------------------------------------
// FP16 tensor-core GEMM: C = A[8192,K] @ Wt^T  (Wt stored [M][K] half).
// 128x128x32 block tile, 256 threads (8 warps, 2x4), 64x32 warp tiles,
// m16n8k16, cp.async double-buffered. Smem stride 40 halves.
// mode 0: fused QKV scatter. Global col c in [0,1536): proj=c>>9.
//         proj 0/1 -> half2 to [B,H,S,Dh]; proj 2 -> half to [B,H,Dh,S].
// mode 1: half2 relu(acc+bias)  -> C[row*M+col]      (FFN1)
// mode 2: fp32 acc+bias+resid   -> C[row*M+col]      (FFN2 + residual)
// ---------------------------------------------------------------------------
#define SH 40
#define GEMM_SMEM (2*(2*128*SH*2))   // 40960 B

__global__ __launch_bounds__(256, 2) void gemm_h(
    const __half* __restrict__ A, const __half* __restrict__ Wt,
    const float* __restrict__ bias, const float* __restrict__ resid,
    void* __restrict__ Cv, int K, int M, int mode)
{
    extern __shared__ __half sm[];
    __half* As = sm;                 // [2][128][SH]
    __half* Bs = sm + 2 * 128 * SH;  // [2][128][SH]

    int tid = threadIdx.x;
    int w = tid >> 5, lane = tid & 31;
    int g = lane >> 2, t4 = lane & 3;
    int wr = w >> 2, wc = w & 3;
    int rowBase = blockIdx.y * 128;
    int colBase = blockIdx.x * 128;

    uint32_t sA = (uint32_t)__cvta_generic_to_shared(As);
    uint32_t sB = (uint32_t)__cvta_generic_to_shared(Bs);

    float acc[4][4][4];
    #pragma unroll
    for (int mf = 0; mf < 4; mf++)
        #pragma unroll
        for (int nf = 0; nf < 4; nf++)
            #pragma unroll
            for (int r = 0; r < 4; r++) acc[mf][nf][r] = 0.f;

    int rr[2], rc[2];
    #pragma unroll
    for (int j = 0; j < 2; j++) {
        int i = tid + 256 * j;
        rr[j] = i >> 2; rc[j] = (i & 3) * 8;
    }

    int nk = K >> 5;

    #pragma unroll
    for (int j = 0; j < 2; j++) {
        cpasync16(sA + (rr[j] * SH + rc[j]) * 2, A + (size_t)(rowBase + rr[j]) * K + rc[j]);
        cpasync16(sB + (rr[j] * SH + rc[j]) * 2, Wt + (size_t)(colBase + rr[j]) * K + rc[j]);
    }
    cpcommit();

    for (int it = 0; it < nk; it++) {
        cpwait0();
        __syncthreads();
        if (it + 1 < nk) {
            int k0 = (it + 1) << 5;
            int buf = (it + 1) & 1;
            #pragma unroll
            for (int j = 0; j < 2; j++) {
                cpasync16(sA + (buf * 128 * SH + rr[j] * SH + rc[j]) * 2,
                          A + (size_t)(rowBase + rr[j]) * K + k0 + rc[j]);
                cpasync16(sB + (buf * 128 * SH + rr[j] * SH + rc[j]) * 2,
                          Wt + (size_t)(colBase + rr[j]) * K + k0 + rc[j]);
            }
            cpcommit();
        }
        const __half* Ab = As + (it & 1) * 128 * SH;
        const __half* Bb = Bs + (it & 1) * 128 * SH;

        #pragma unroll
        for (int ks = 0; ks < 32; ks += 16) {
            uint32_t a[4][4], bf[4][2];
            #pragma unroll
            for (int mf = 0; mf < 4; mf++) {
                int r0 = wr * 64 + mf * 16 + g;
                a[mf][0] = ldh2(Ab + r0 * SH + ks + 2 * t4);
                a[mf][1] = ldh2(Ab + (r0 + 8) * SH + ks + 2 * t4);
                a[mf][2] = ldh2(Ab + r0 * SH + ks + 8 + 2 * t4);
                a[mf][3] = ldh2(Ab + (r0 + 8) * SH + ks + 8 + 2 * t4);
            }
            #pragma unroll
            for (int nf = 0; nf < 4; nf++) {
                int n0 = wc * 32 + nf * 8 + g;
                bf[nf][0] = ldh2(Bb + n0 * SH + ks + 2 * t4);
                bf[nf][1] = ldh2(Bb + n0 * SH + ks + 8 + 2 * t4);
            }
            #pragma unroll
            for (int mf = 0; mf < 4; mf++)
                #pragma unroll
                for (int nf = 0; nf < 4; nf++)
                    mma_f16(acc[mf][nf], a[mf], bf[nf]);
        }
        __syncthreads();
    }

    // Epilogue
    #pragma unroll
    for (int mf = 0; mf < 4; mf++) {
        int r0 = rowBase + wr * 64 + mf * 16 + g;
        #pragma unroll
        for (int nf = 0; nf < 4; nf++) {
            int c0 = colBase + wc * 32 + nf * 8 + 2 * t4;
            float b0 = bias[c0], b1 = bias[c0 + 1];
            #pragma unroll
            for (int half_ = 0; half_ < 2; half_++) {
                int row = r0 + half_ * 8;
                float v0 = acc[mf][nf][half_ * 2 + 0] + b0;
                float v1 = acc[mf][nf][half_ * 2 + 1] + b1;
                if (mode == 0) {
                    int proj = c0 >> 9;
                    int cl = c0 & 511;
                    int b_ = row >> 11, s = row & 2047, h = cl >> 6, d = cl & 63;
                    __half* base = (__half*)Cv + (size_t)proj * 4194304u;
                    if (proj < 2) {
                        __half2* C = (__half2*)(base +
                            ((((size_t)b_ * N_HEADS + h) * SEQ + s) * DH + d));
                        *C = __floats2half2_rn(v0, v1);
                    } else {
                        size_t vo = (((size_t)b_ * N_HEADS + h) * DH + d) * SEQ + s;
                        base[vo] = __float2half(v0);
                        base[vo + SEQ] = __float2half(v1);
                    }
                } else if (mode == 1) {
                    __half2* C = (__half2*)((__half*)Cv + (size_t)row * M + c0);
                    *C = __floats2half2_rn(fmaxf(v0, 0.f), fmaxf(v1, 0.f));
                } else {
                    float2 rv = *(const float2*)(resid + (size_t)row * M + c0);
                    *(float2*)((float*)Cv + (size_t)row * M + c0) =
                        make_float2(v0 + rv.x, v1 + rv.y);
                }
            }
        }
    }
}

// ---------------------------------------------------------------------------
// Sigmoid-pointwise attention, fp16 tensor cores.
// Block = (b, h, 128 q-rows), 512 threads (16 warps). K/V tiles of 128 t.
// mm1: P = Q K^T (4x4 warps, 32x32 tiles); sigmoid via tanh.approx.f16x2;
// mm2: O += P V (8x2 warps, 16x32 tiles). V stored [d][s] in gmem.
// Smem (halves): Qs[128][72] Ks[128][72] Vs[64][136] Ps[128][136] = 89088 B.
// 2 blocks/SM resident.
// ---------------------------------------------------------------------------
#define AQ 72
#define AV 136
#define ATTN_SMEM ((128*AQ + 128*AQ + 64*AV + 128*AV) * 2)

__global__ __launch_bounds__(512, 2) void attn_h(
    const __half* __restrict__ q, const __half* __restrict__ kk,
    const __half* __restrict__ vv, const float* __restrict__ x,
    float* __restrict__ x1)
{
    extern __shared__ __half sm[];
    __half* Qs = sm;                 // [128][AQ]  [s][d]
    __half* Ks = Qs + 128 * AQ;      // [128][AQ]  [t][d]
    __half* Vs = Ks + 128 * AQ;      // [64][AV]   [d][t]
    __half* Ps = Vs + 64 * AV;       // [128][AV]  [s][t]

    int b = blockIdx.z, h = blockIdx.y;
    int s0 = blockIdx.x * 128;
    const __half* qbase = q + (((size_t)b * N_HEADS + h) * SEQ + s0) * DH;
    const __half* kbase = kk + ((size_t)b * N_HEADS + h) * SEQ * DH;
    const __half* vbase = vv + ((size_t)b * N_HEADS + h) * DH * SEQ;

    int tid = threadIdx.x, w = tid >> 5, lane = tid & 31;
    int g = lane >> 2, t4 = lane & 3;
    int wr1 = w >> 2, wc1 = w & 3;   // mm1: 4x4 grid of 32x32
    int wr2 = w >> 1, wc2 = w & 1;   // mm2: 8x2 grid of 16x32

    for (int i = tid; i < 1024; i += 512) {
        int r = i >> 3, c = (i & 7) * 8;
        *(float4*)(Qs + r * AQ + c) = *(const float4*)(qbase + (size_t)r * DH + c);
    }

    float o[4][4];
    #pragma unroll
    for (int nf = 0; nf < 4; nf++)
        #pragma unroll
        for (int r = 0; r < 4; r++) o[nf][r] = 0.f;

    const float hscale = 0.5f * 0.04419417382415922f;  // 0.5/sqrt(512)

    for (int t0 = 0; t0 < SEQ; t0 += 128) {
        __syncthreads();
        for (int i = tid; i < 1024; i += 512) {
            int r = i >> 3, c = (i & 7) * 8;
            *(float4*)(Ks + r * AQ + c) = *(const float4*)(kbase + (size_t)(t0 + r) * DH + c);
        }
        for (int i = tid; i < 1024; i += 512) {
            int d = i >> 4, c = (i & 15) * 8;
            *(float4*)(Vs + d * AV + c) = *(const float4*)(vbase + (size_t)d * SEQ + t0 + c);
        }
        __syncthreads();

        // mm1: P = Q K^T
        float p[2][4][4];
        #pragma unroll
        for (int mf = 0; mf < 2; mf++)
            #pragma unroll
            for (int nf = 0; nf < 4; nf++)
                #pragma unroll
                for (int r = 0; r < 4; r++) p[mf][nf][r] = 0.f;

        #pragma unroll
        for (int ks = 0; ks < 64; ks += 16) {
            uint32_t a[2][4], bf[4][2];
            #pragma unroll
            for (int mf = 0; mf < 2; mf++) {
                int r0 = wr1 * 32 + mf * 16 + g;
                a[mf][0] = ldh2(Qs + r0 * AQ + ks + 2 * t4);
                a[mf][1] = ldh2(Qs + (r0 + 8) * AQ + ks + 2 * t4);
                a[mf][2] = ldh2(Qs + r0 * AQ + ks + 8 + 2 * t4);
                a[mf][3] = ldh2(Qs + (r0 + 8) * AQ + ks + 8 + 2 * t4);
            }
            #pragma unroll
            for (int nf = 0; nf < 4; nf++) {
                int n0 = wc1 * 32 + nf * 8 + g;
                bf[nf][0] = ldh2(Ks + n0 * AQ + ks + 2 * t4);
                bf[nf][1] = ldh2(Ks + n0 * AQ + ks + 8 + 2 * t4);
            }
            #pragma unroll
            for (int mf = 0; mf < 2; mf++)
                #pragma unroll
                for (int nf = 0; nf < 4; nf++)
                    mma_f16(p[mf][nf], a[mf], bf[nf]);
        }

        // sigmoid via tanh.approx.f16x2 -> half2 Ps[s][t]
        #pragma unroll
        for (int mf = 0; mf < 2; mf++) {
            int r0 = wr1 * 32 + mf * 16 + g;
            #pragma unroll
            for (int nf = 0; nf < 4; nf++) {
                int c0 = wc1 * 32 + nf * 8 + 2 * t4;
                #pragma unroll
                for (int half_ = 0; half_ < 2; half_++) {
                    int rw = r0 + half_ * 8;
                    uint32_t r2 = sigmoid_h2(p[mf][nf][half_ * 2 + 0] * hscale,
                                             p[mf][nf][half_ * 2 + 1] * hscale);
                    *(uint32_t*)(Ps + rw * AV + c0) = r2;
                }
            }
        }
        __syncthreads();

        // mm2: O += P V
        #pragma unroll
        for (int ks = 0; ks < 128; ks += 16) {
            uint32_t a[4], bf[4][2];
            int r0 = wr2 * 16 + g;
            a[0] = ldh2(Ps + r0 * AV + ks + 2 * t4);
            a[1] = ldh2(Ps + (r0 + 8) * AV + ks + 2 * t4);
            a[2] = ldh2(Ps + r0 * AV + ks + 8 + 2 * t4);
            a[3] = ldh2(Ps + (r0 + 8) * AV + ks + 8 + 2 * t4);
            #pragma unroll
            for (int nf = 0; nf < 4; nf++) {
                int d0 = wc2 * 32 + nf * 8 + g;
                bf[nf][0] = ldh2(Vs + d0 * AV + ks + 2 * t4);
                bf[nf][1] = ldh2(Vs + d0 * AV + ks + 8 + 2 * t4);
            }
            #pragma unroll
            for (int nf = 0; nf < 4; nf++)
                mma_f16(o[nf], a, bf[nf]);
        }
    }

    // Epilogue: x1 = x + O
    int r0 = wr2 * 16 + g;
    #pragma unroll
    for (int nf = 0; nf < 4; nf++) {
        int col = h * DH + wc2 * 32 + nf * 8 + 2 * t4;
        #pragma unroll
        for (int half_ = 0; half_ < 2; half_++) {
            int s = s0 + r0 + half_ * 8;
            size_t idx = ((size_t)(b * SEQ + s)) * D_MODEL + col;
            float2 xr = *(const float2*)(x + idx);
            *(float2*)(x1 + idx) = make_float2(xr.x + o[nf][half_ * 2 + 0],
                                               xr.y + o[nf][half_ * 2 + 1]);
        }
    }
}

// ---------------------------------------------------------------------------
// kernel_launch
// ---------------------------------------------------------------------------
extern "C" void kernel_launch(void* const* d_in, const int* in_sizes, int n_in,
                              void* d_out, int out_size)
{
    (void)in_sizes; (void)n_in; (void)out_size;
    const float* x   = (const float*)d_in[0];
    const float* Wq  = (const float*)d_in[1];
    const float* bq  = (const float*)d_in[2];
    const float* Wk  = (const float*)d_in[3];
    const float* bk  = (const float*)d_in[4];
    const float* Wv  = (const float*)d_in[5];
    const float* bv  = (const float*)d_in[6];
    const float* W1  = (const float*)d_in[7];
    const float* b1  = (const float*)d_in[8];
    const float* W2  = (const float*)d_in[9];
    const float* b2  = (const float*)d_in[10];
    const float* g1  = (const float*)d_in[11];
    const float* be1 = (const float*)d_in[12];
    const float* g2  = (const float*)d_in[13];
    const float* be2 = (const float*)d_in[14];
    float* out = (float*)d_out;

    float* scratch = nullptr;
    cudaGetSymbolAddress((void**)&scratch, g_scratch);
    __half* xn1 = (__half*)(scratch + OFF_XN1);
    __half* qb  = (__half*)(scratch + OFF_Q);
    __half* kb  = (__half*)(scratch + OFF_K);
    __half* vb  = (__half*)(scratch + OFF_V);
    float*  x1  = scratch + OFF_X1;
    __half* xn2 = (__half*)(scratch + OFF_XN2);
    __half* mid = (__half*)(scratch + OFF_MID);
    __half* wqkv = (__half*)(scratch + OFF_WQKV);
    __half* w1t = (__half*)(scratch + OFF_W1);
    __half* w2t = (__half*)(scratch + OFF_W2);
    float*  bqkv = scratch + OFF_BQKV;

    cudaFuncSetAttribute(gemm_h, cudaFuncAttributeMaxDynamicSharedMemorySize, GEMM_SMEM);
    cudaFuncSetAttribute(attn_h, cudaFuncAttributeMaxDynamicSharedMemorySize, ATTN_SMEM);

    dim3 tb(32, 8);
    // Transpose+convert weights to half [out][in]; QKV stacked into one buffer.
    transpose_half_kernel<<<dim3(16, 16), tb>>>(Wq, wqkv, 512, 512);
    transpose_half_kernel<<<dim3(16, 16), tb>>>(Wk, wqkv + 512 * 512, 512, 512);
    transpose_half_kernel<<<dim3(16, 16), tb>>>(Wv, wqkv + 2 * 512 * 512, 512, 512);
    transpose_half_kernel<<<dim3(64, 16), tb>>>(W1, w1t, 512, 2048);
    transpose_half_kernel<<<dim3(16, 64), tb>>>(W2, w2t, 2048, 512);
    concat_bias_kernel<<<1, 512>>>(bq, bk, bv, bqkv);

    // LN1 -> half
    ln_kernel<<<NROWS, 256>>>(x, g1, be1, xn1);
    // Fused QKV projection (Q,K: [B,H,S,Dh]; V: [B,H,Dh,S])
    gemm_h<<<dim3(12, 64), 256, GEMM_SMEM>>>(xn1, wqkv, bqkv, nullptr, qb, 512, 1536, 0);
    // Sigmoid attention + residual -> x1 (fp32)
    attn_h<<<dim3(16, 8, 4), 512, ATTN_SMEM>>>(qb, kb, vb, x, x1);
    // LN2 -> half
    ln_kernel<<<NROWS, 256>>>(x1, g2, be2, xn2);
    // FFN
    gemm_h<<<dim3(16, 64), 256, GEMM_SMEM>>>(xn2, w1t, b1, nullptr, mid, 512, 2048, 1);
    gemm_h<<<dim3(4, 64), 256, GEMM_SMEM>>>(mid, w2t, b2, x1, out, 2048, 512, 2);
}

// round 8
// speedup vs baseline: 6.1888x; 1.0779x over previous
#include <cuda_runtime.h>
#include <cuda_fp16.h>
#include <math.h>
#include <stdint.h>

// Problem constants
#define D_MODEL 512
#define N_HEADS 8
#define DH      64
#define D_FF    2048
#define BATCH   4
#define SEQ     2048
#define NROWS   (BATCH*SEQ)   // 8192

// ---------------------------------------------------------------------------
// Scratch (allocation-free rule). Offsets in floats; half buffers reinterpret.
// ---------------------------------------------------------------------------
__device__ __align__(256) float g_scratch[25165824];

#define OFF_XN1  0u          // half [8192][512]
#define OFF_Q    2097152u    // half [B][H][S][Dh]
#define OFF_K    4194304u    // half [B][H][S][Dh]
#define OFF_V    6291456u    // half [B][H][Dh][S]  (transposed!)
#define OFF_X1   8388608u    // float [8192][512]
#define OFF_XN2  12582912u   // half [8192][512]
#define OFF_MID  14680064u   // half [8192][2048]
#define OFF_WQKV 23068672u   // half [1536][512]  (transposed [out][in], Q|K|V)
#define OFF_W1   23461888u   // half [2048][512]
#define OFF_W2   23986176u   // half [512][2048]
#define OFF_BQKV 24510464u   // float [1536]

// ---------------------------------------------------------------------------
// Helpers
// ---------------------------------------------------------------------------
__device__ __forceinline__ void mma_f16(float* d, const uint32_t* a, const uint32_t* b) {
    asm volatile(
        "mma.sync.aligned.m16n8k16.row.col.f32.f16.f16.f32 "
        "{%0,%1,%2,%3}, {%4,%5,%6,%7}, {%8,%9}, {%0,%1,%2,%3};\n"
        : "+f"(d[0]), "+f"(d[1]), "+f"(d[2]), "+f"(d[3])
        : "r"(a[0]), "r"(a[1]), "r"(a[2]), "r"(a[3]), "r"(b[0]), "r"(b[1]));
}

__device__ __forceinline__ uint32_t ldh2(const __half* p) {
    return *(const uint32_t*)p;
}

__device__ __forceinline__ uint32_t sigmoid_h2(float z0, float z1) {
    // sigmoid(z) = 0.5 + 0.5*tanh(0.5*z); inputs are already 0.5*scale*score
    __half2 hz = __floats2half2_rn(z0, z1);
    uint32_t u = *(uint32_t*)&hz;
    uint32_t t;
    asm("tanh.approx.f16x2 %0, %1;" : "=r"(t) : "r"(u));
    __half2 th = *(__half2*)&t;
    __half2 r = __hfma2(th, __float2half2_rn(0.5f), __float2half2_rn(0.5f));
    return *(uint32_t*)&r;
}

__device__ __forceinline__ void cpasync16(uint32_t s, const void* g) {
    asm volatile("cp.async.cg.shared.global [%0], [%1], 16;" :: "r"(s), "l"(g));
}
__device__ __forceinline__ void cpcommit() { asm volatile("cp.async.commit_group;"); }
__device__ __forceinline__ void cpwait0()  { asm volatile("cp.async.wait_group 0;"); }
__device__ __forceinline__ void cpwait1()  { asm volatile("cp.async.wait_group 1;"); }

__device__ __forceinline__ uint32_t smem_u32(const void* p) {
    return (uint32_t)__cvta_generic_to_shared(p);
}

// ---------------------------------------------------------------------------
// Fused weight convert + transpose: 5 weights, one launch.
// Tile map (32x32 tiles, block (32,8)):
//   [0,768):    Wq/Wk/Wv (256 tiles each) -> wqkv stacked, K=512,M=512
//   [768,1792): W1 -> w1t, K=512,  M=2048
//   [1792,2816):W2 -> w2t, K=2048, M=512
// ---------------------------------------------------------------------------
__global__ __launch_bounds__(256) void transpose_all_kernel(
    const float* __restrict__ Wq, const float* __restrict__ Wk,
    const float* __restrict__ Wv, const float* __restrict__ W1,
    const float* __restrict__ W2,
    __half* __restrict__ wqkv, __half* __restrict__ w1t, __half* __restrict__ w2t)
{
    __shared__ float t[32][33];
    int tb = blockIdx.x;
    const float* W; __half* Wt; int K, M, mcols;
    if (tb < 768) {
        int wsel = tb >> 8; tb &= 255;
        W = (wsel == 0) ? Wq : (wsel == 1) ? Wk : Wv;
        Wt = wqkv + (size_t)wsel * 262144u;
        K = 512; M = 512; mcols = 16;
    } else if (tb < 1792) {
        tb -= 768; W = W1; Wt = w1t; K = 512; M = 2048; mcols = 64;
    } else {
        tb -= 1792; W = W2; Wt = w2t; K = 2048; M = 512; mcols = 16;
    }
    int m0 = (tb % mcols) * 32, k0 = (tb / mcols) * 32;
    int tx = threadIdx.x, ty = threadIdx.y;
    #pragma unroll
    for (int j = 0; j < 4; j++) {
        int kr = ty + j * 8;
        t[kr][tx] = W[(size_t)(k0 + kr) * M + m0 + tx];
    }
    __syncthreads();
    #pragma unroll
    for (int j = 0; j < 4; j++) {
        int mr = ty + j * 8;
        Wt[(size_t)(m0 + mr) * K + k0 + tx] = __float2half(t[tx][mr]);
    }
}

// Concat three 512-float bias vectors.
__global__ __launch_bounds__(512) void concat_bias_kernel(
    const float* __restrict__ a, const float* __restrict__ b,
    const float* __restrict__ c, float* __restrict__ o)
{
    int t = threadIdx.x;
    o[t] = a[t]; o[512 + t] = b[t]; o[1024 + t] = c[t];
}

// ---------------------------------------------------------------------------
// LayerNorm: block per row, 256 threads, half output.
// ---------------------------------------------------------------------------
__global__ __launch_bounds__(256) void ln_kernel(
    const float* __restrict__ x, const float* __restrict__ g,
    const float* __restrict__ b, __half* __restrict__ y)
{
    int row = blockIdx.x;
    int t = threadIdx.x;
    const float2* xr = (const float2*)(x + (size_t)row * D_MODEL);
    __half2* yr = (__half2*)(y + (size_t)row * D_MODEL);
    float2 v = xr[t];

    __shared__ float red[8];

    float s = v.x + v.y;
    #pragma unroll
    for (int o = 16; o > 0; o >>= 1) s += __shfl_xor_sync(0xffffffffu, s, o);
    if ((t & 31) == 0) red[t >> 5] = s;
    __syncthreads();
    float tot = 0.f;
    #pragma unroll
    for (int i = 0; i < 8; i++) tot += red[i];
    float mu = tot * (1.0f / D_MODEL);
    __syncthreads();

    float d0 = v.x - mu, d1 = v.y - mu;
    s = d0 * d0 + d1 * d1;
    #pragma unroll
    for (int o = 16; o > 0; o >>= 1) s += __shfl_xor_sync(0xffffffffu, s, o);
    if ((t & 31) == 0) red[t >> 5] = s;
    __syncthreads();
    tot = 0.f;
    #pragma unroll
    for (int i = 0; i < 8; i++) tot += red[i];
    float inv = rsqrtf(tot * (1.0f / D_MODEL) + 1e-5f);

    float2 gg = ((const float2*)g)[t];
    float2 bb = ((const float2*)b)[t];
    yr[t] = __floats2half2_rn(d0 * inv * gg.x + bb.x, d1 * inv * gg.y + bb.y);
}

// ---------------------------------------------------------------------------
// FP16 tensor-core GEMM: C = A[8192,K] @ Wt^T  (Wt stored [M][K] half).
// 128x128x32 block tile, 256 threads (8 warps, 2x4), 64x32 warp tiles,
// m16n8k16, cp.async double-buffered. Smem stride 40 halves.
// mode 0: fused QKV scatter. Global col c in [0,1536): proj=c>>9.
//         proj 0/1 -> half2 to [B,H,S,Dh]; proj 2 -> half to [B,H,Dh,S].
// mode 1: half2 relu(acc+bias)  -> C[row*M+col]      (FFN1)
// mode 2: fp32 acc+bias+resid   -> C[row*M+col]      (FFN2 + residual)
// ---------------------------------------------------------------------------
#define SH 40
#define GEMM_SMEM (2*(2*128*SH*2))   // 40960 B

__global__ __launch_bounds__(256, 2) void gemm_h(
    const __half* __restrict__ A, const __half* __restrict__ Wt,
    const float* __restrict__ bias, const float* __restrict__ resid,
    void* __restrict__ Cv, int K, int M, int mode)
{
    extern __shared__ __half sm[];
    __half* As = sm;                 // [2][128][SH]
    __half* Bs = sm + 2 * 128 * SH;  // [2][128][SH]

    int tid = threadIdx.x;
    int w = tid >> 5, lane = tid & 31;
    int g = lane >> 2, t4 = lane & 3;
    int wr = w >> 2, wc = w & 3;
    int rowBase = blockIdx.y * 128;
    int colBase = blockIdx.x * 128;

    uint32_t sA = smem_u32(As);
    uint32_t sB = smem_u32(Bs);

    float acc[4][4][4];
    #pragma unroll
    for (int mf = 0; mf < 4; mf++)
        #pragma unroll
        for (int nf = 0; nf < 4; nf++)
            #pragma unroll
            for (int r = 0; r < 4; r++) acc[mf][nf][r] = 0.f;

    int rr[2], rc[2];
    #pragma unroll
    for (int j = 0; j < 2; j++) {
        int i = tid + 256 * j;
        rr[j] = i >> 2; rc[j] = (i & 3) * 8;
    }

    int nk = K >> 5;

    #pragma unroll
    for (int j = 0; j < 2; j++) {
        cpasync16(sA + (rr[j] * SH + rc[j]) * 2, A + (size_t)(rowBase + rr[j]) * K + rc[j]);
        cpasync16(sB + (rr[j] * SH + rc[j]) * 2, Wt + (size_t)(colBase + rr[j]) * K + rc[j]);
    }
    cpcommit();

    for (int it = 0; it < nk; it++) {
        cpwait0();
        __syncthreads();
        if (it + 1 < nk) {
            int k0 = (it + 1) << 5;
            int buf = (it + 1) & 1;
            #pragma unroll
            for (int j = 0; j < 2; j++) {
                cpasync16(sA + (buf * 128 * SH + rr[j] * SH + rc[j]) * 2,
                          A + (size_t)(rowBase + rr[j]) * K + k0 + rc[j]);
                cpasync16(sB + (buf * 128 * SH + rr[j] * SH + rc[j]) * 2,
                          Wt + (size_t)(colBase + rr[j]) * K + k0 + rc[j]);
            }
            cpcommit();
        }
        const __half* Ab = As + (it & 1) * 128 * SH;
        const __half* Bb = Bs + (it & 1) * 128 * SH;

        #pragma unroll
        for (int ks = 0; ks < 32; ks += 16) {
            uint32_t a[4][4], bf[4][2];
            #pragma unroll
            for (int mf = 0; mf < 4; mf++) {
                int r0 = wr * 64 + mf * 16 + g;
                a[mf][0] = ldh2(Ab + r0 * SH + ks + 2 * t4);
                a[mf][1] = ldh2(Ab + (r0 + 8) * SH + ks + 2 * t4);
                a[mf][2] = ldh2(Ab + r0 * SH + ks + 8 + 2 * t4);
                a[mf][3] = ldh2(Ab + (r0 + 8) * SH + ks + 8 + 2 * t4);
            }
            #pragma unroll
            for (int nf = 0; nf < 4; nf++) {
                int n0 = wc * 32 + nf * 8 + g;
                bf[nf][0] = ldh2(Bb + n0 * SH + ks + 2 * t4);
                bf[nf][1] = ldh2(Bb + n0 * SH + ks + 8 + 2 * t4);
            }
            #pragma unroll
            for (int mf = 0; mf < 4; mf++)
                #pragma unroll
                for (int nf = 0; nf < 4; nf++)
                    mma_f16(acc[mf][nf], a[mf], bf[nf]);
        }
        __syncthreads();
    }

    // Epilogue
    #pragma unroll
    for (int mf = 0; mf < 4; mf++) {
        int r0 = rowBase + wr * 64 + mf * 16 + g;
        #pragma unroll
        for (int nf = 0; nf < 4; nf++) {
            int c0 = colBase + wc * 32 + nf * 8 + 2 * t4;
            float b0 = bias[c0], b1 = bias[c0 + 1];
            #pragma unroll
            for (int half_ = 0; half_ < 2; half_++) {
                int row = r0 + half_ * 8;
                float v0 = acc[mf][nf][half_ * 2 + 0] + b0;
                float v1 = acc[mf][nf][half_ * 2 + 1] + b1;
                if (mode == 0) {
                    int proj = c0 >> 9;
                    int cl = c0 & 511;
                    int b_ = row >> 11, s = row & 2047, h = cl >> 6, d = cl & 63;
                    __half* base = (__half*)Cv + (size_t)proj * 4194304u;
                    if (proj < 2) {
                        __half2* C = (__half2*)(base +
                            ((((size_t)b_ * N_HEADS + h) * SEQ + s) * DH + d));
                        *C = __floats2half2_rn(v0, v1);
                    } else {
                        size_t vo = (((size_t)b_ * N_HEADS + h) * DH + d) * SEQ + s;
                        base[vo] = __float2half(v0);
                        base[vo + SEQ] = __float2half(v1);
                    }
                } else if (mode == 1) {
                    __half2* C = (__half2*)((__half*)Cv + (size_t)row * M + c0);
                    *C = __floats2half2_rn(fmaxf(v0, 0.f), fmaxf(v1, 0.f));
                } else {
                    float2 rv = *(const float2*)(resid + (size_t)row * M + c0);
                    *(float2*)((float*)Cv + (size_t)row * M + c0) =
                        make_float2(v0 + rv.x, v1 + rv.y);
                }
            }
        }
    }
}

// ---------------------------------------------------------------------------
// Sigmoid-pointwise attention, fp16 tensor cores + cp.async pipelining.
// Block = (b, h, 128 q-rows), 512 threads (16 warps). K/V tiles of 128 t.
// K double-buffered: K(t+1) prefetched during tile t compute.
// V single-buffered: V(t+1) issued right after mm2(t), overlaps mm1(t+1).
// Commit-group order per tile: [..., V(t)], K(t+1) -> wait1 at top (K ready),
// wait1 mid (V ready). Last tile uses wait0.
// Smem (halves): Qs[128][72] Ks[2][128][72] Vs[64][136] Ps[128][136] = 105 KB.
// 2 blocks/SM resident.
// ---------------------------------------------------------------------------
#define AQ 72
#define AV 136
#define ATTN_SMEM ((128*AQ + 2*128*AQ + 64*AV + 128*AV) * 2)   // 107520

__global__ __launch_bounds__(512, 2) void attn_h(
    const __half* __restrict__ q, const __half* __restrict__ kk,
    const __half* __restrict__ vv, const float* __restrict__ x,
    float* __restrict__ x1)
{
    extern __shared__ __half sm[];
    __half* Qs = sm;                     // [128][AQ]  [s][d]
    __half* Ks = Qs + 128 * AQ;          // [2][128][AQ]  [t][d]
    __half* Vs = Ks + 2 * 128 * AQ;      // [64][AV]   [d][t]
    __half* Ps = Vs + 64 * AV;           // [128][AV]  [s][t]

    int b = blockIdx.z, h = blockIdx.y;
    int s0 = blockIdx.x * 128;
    const __half* qbase = q + (((size_t)b * N_HEADS + h) * SEQ + s0) * DH;
    const __half* kbase = kk + ((size_t)b * N_HEADS + h) * SEQ * DH;
    const __half* vbase = vv + ((size_t)b * N_HEADS + h) * DH * SEQ;

    int tid = threadIdx.x, w = tid >> 5, lane = tid & 31;
    int g = lane >> 2, t4 = lane & 3;
    int wr1 = w >> 2, wc1 = w & 3;   // mm1: 4x4 grid of 32x32
    int wr2 = w >> 1, wc2 = w & 1;   // mm2: 8x2 grid of 16x32

    uint32_t qS = smem_u32(Qs);
    uint32_t kS = smem_u32(Ks);
    uint32_t vS = smem_u32(Vs);

    // indices for async loads (2 chunks of 16B each for K and for V)
    int kr[2], kc[2], vd[2], vc[2];
    #pragma unroll
    for (int j = 0; j < 2; j++) {
        int i = tid + 512 * j;
        kr[j] = i >> 3;  kc[j] = (i & 7) * 8;     // 128 rows x 8 chunks
        vd[j] = i >> 4;  vc[j] = (i & 15) * 8;    // 64 rows x 16 chunks
    }

    // Prologue: Q + K(0) in group A; V(0) in group B.
    #pragma unroll
    for (int j = 0; j < 2; j++) {
        cpasync16(qS + (kr[j] * AQ + kc[j]) * 2, qbase + (size_t)kr[j] * DH + kc[j]);
        cpasync16(kS + (kr[j] * AQ + kc[j]) * 2, kbase + (size_t)kr[j] * DH + kc[j]);
    }
    cpcommit();
    #pragma unroll
    for (int j = 0; j < 2; j++)
        cpasync16(vS + (vd[j] * AV + vc[j]) * 2, vbase + (size_t)vd[j] * SEQ + vc[j]);
    cpcommit();

    float o[4][4];
    #pragma unroll
    for (int nf = 0; nf < 4; nf++)
        #pragma unroll
        for (int r = 0; r < 4; r++) o[nf][r] = 0.f;

    const float hscale = 0.5f * 0.04419417382415922f;  // 0.5/sqrt(512)

    int buf = 0;
    for (int t0 = 0; t0 < SEQ; t0 += 128) {
        bool more = (t0 + 128 < SEQ);
        // K(t) (and Q on first iter) ready; V(t) may still be in flight.
        cpwait1();
        __syncthreads();

        // Prefetch K(t+1) into other buffer.
        if (more) {
            uint32_t kd = kS + (buf ^ 1) * 128 * AQ * 2;
            #pragma unroll
            for (int j = 0; j < 2; j++)
                cpasync16(kd + (kr[j] * AQ + kc[j]) * 2,
                          kbase + (size_t)(t0 + 128 + kr[j]) * DH + kc[j]);
            cpcommit();
        }

        const __half* Kb = Ks + buf * 128 * AQ;

        // mm1: P = Q K^T
        float p[2][4][4];
        #pragma unroll
        for (int mf = 0; mf < 2; mf++)
            #pragma unroll
            for (int nf = 0; nf < 4; nf++)
                #pragma unroll
                for (int r = 0; r < 4; r++) p[mf][nf][r] = 0.f;

        #pragma unroll
        for (int ks = 0; ks < 64; ks += 16) {
            uint32_t a[2][4], bf[4][2];
            #pragma unroll
            for (int mf = 0; mf < 2; mf++) {
                int r0 = wr1 * 32 + mf * 16 + g;
                a[mf][0] = ldh2(Qs + r0 * AQ + ks + 2 * t4);
                a[mf][1] = ldh2(Qs + (r0 + 8) * AQ + ks + 2 * t4);
                a[mf][2] = ldh2(Qs + r0 * AQ + ks + 8 + 2 * t4);
                a[mf][3] = ldh2(Qs + (r0 + 8) * AQ + ks + 8 + 2 * t4);
            }
            #pragma unroll
            for (int nf = 0; nf < 4; nf++) {
                int n0 = wc1 * 32 + nf * 8 + g;
                bf[nf][0] = ldh2(Kb + n0 * AQ + ks + 2 * t4);
                bf[nf][1] = ldh2(Kb + n0 * AQ + ks + 8 + 2 * t4);
            }
            #pragma unroll
            for (int mf = 0; mf < 2; mf++)
                #pragma unroll
                for (int nf = 0; nf < 4; nf++)
                    mma_f16(p[mf][nf], a[mf], bf[nf]);
        }

        // sigmoid via tanh.approx.f16x2 -> half2 Ps[s][t]
        #pragma unroll
        for (int mf = 0; mf < 2; mf++) {
            int r0 = wr1 * 32 + mf * 16 + g;
            #pragma unroll
            for (int nf = 0; nf < 4; nf++) {
                int c0 = wc1 * 32 + nf * 8 + 2 * t4;
                #pragma unroll
                for (int half_ = 0; half_ < 2; half_++) {
                    int rw = r0 + half_ * 8;
                    uint32_t r2 = sigmoid_h2(p[mf][nf][half_ * 2 + 0] * hscale,
                                             p[mf][nf][half_ * 2 + 1] * hscale);
                    *(uint32_t*)(Ps + rw * AV + c0) = r2;
                }
            }
        }

        // V(t) must be complete before mm2 (pending groups: [V(t), K(t+1)] -> wait1;
        // last tile: [V(t)] only -> wait0).
        if (more) cpwait1(); else cpwait0();
        __syncthreads();   // Ps + Vs visible

        // mm2: O += P V
        #pragma unroll
        for (int ks = 0; ks < 128; ks += 16) {
            uint32_t a[4], bf[4][2];
            int r0 = wr2 * 16 + g;
            a[0] = ldh2(Ps + r0 * AV + ks + 2 * t4);
            a[1] = ldh2(Ps + (r0 + 8) * AV + ks + 2 * t4);
            a[2] = ldh2(Ps + r0 * AV + ks + 8 + 2 * t4);
            a[3] = ldh2(Ps + (r0 + 8) * AV + ks + 8 + 2 * t4);
            #pragma unroll
            for (int nf = 0; nf < 4; nf++) {
                int d0 = wc2 * 32 + nf * 8 + g;
                bf[nf][0] = ldh2(Vs + d0 * AV + ks + 2 * t4);
                bf[nf][1] = ldh2(Vs + d0 * AV + ks + 8 + 2 * t4);
            }
            #pragma unroll
            for (int nf = 0; nf < 4; nf++)
                mma_f16(o[nf], a, bf[nf]);
        }

        __syncthreads();   // everyone done reading Vs (and Ps)

        // Issue V(t+1); completes during next tile's mm1.
        if (more) {
            #pragma unroll
            for (int j = 0; j < 2; j++)
                cpasync16(vS + (vd[j] * AV + vc[j]) * 2,
                          vbase + (size_t)vd[j] * SEQ + t0 + 128 + vc[j]);
            cpcommit();
        }
        buf ^= 1;
    }

    // Epilogue: x1 = x + O
    int r0 = wr2 * 16 + g;
    #pragma unroll
    for (int nf = 0; nf < 4; nf++) {
        int col = h * DH + wc2 * 32 + nf * 8 + 2 * t4;
        #pragma unroll
        for (int half_ = 0; half_ < 2; half_++) {
            int s = s0 + r0 + half_ * 8;
            size_t idx = ((size_t)(b * SEQ + s)) * D_MODEL + col;
            float2 xr = *(const float2*)(x + idx);
            *(float2*)(x1 + idx) = make_float2(xr.x + o[nf][half_ * 2 + 0],
                                               xr.y + o[nf][half_ * 2 + 1]);
        }
    }
}

// ---------------------------------------------------------------------------
// kernel_launch
// ---------------------------------------------------------------------------
extern "C" void kernel_launch(void* const* d_in, const int* in_sizes, int n_in,
                              void* d_out, int out_size)
{
    (void)in_sizes; (void)n_in; (void)out_size;
    const float* x   = (const float*)d_in[0];
    const float* Wq  = (const float*)d_in[1];
    const float* bq  = (const float*)d_in[2];
    const float* Wk  = (const float*)d_in[3];
    const float* bk  = (const float*)d_in[4];
    const float* Wv  = (const float*)d_in[5];
    const float* bv  = (const float*)d_in[6];
    const float* W1  = (const float*)d_in[7];
    const float* b1  = (const float*)d_in[8];
    const float* W2  = (const float*)d_in[9];
    const float* b2  = (const float*)d_in[10];
    const float* g1  = (const float*)d_in[11];
    const float* be1 = (const float*)d_in[12];
    const float* g2  = (const float*)d_in[13];
    const float* be2 = (const float*)d_in[14];
    float* out = (float*)d_out;

    float* scratch = nullptr;
    cudaGetSymbolAddress((void**)&scratch, g_scratch);
    __half* xn1 = (__half*)(scratch + OFF_XN1);
    __half* qb  = (__half*)(scratch + OFF_Q);
    __half* kb  = (__half*)(scratch + OFF_K);
    __half* vb  = (__half*)(scratch + OFF_V);
    float*  x1  = scratch + OFF_X1;
    __half* xn2 = (__half*)(scratch + OFF_XN2);
    __half* mid = (__half*)(scratch + OFF_MID);
    __half* wqkv = (__half*)(scratch + OFF_WQKV);
    __half* w1t = (__half*)(scratch + OFF_W1);
    __half* w2t = (__half*)(scratch + OFF_W2);
    float*  bqkv = scratch + OFF_BQKV;

    cudaFuncSetAttribute(gemm_h, cudaFuncAttributeMaxDynamicSharedMemorySize, GEMM_SMEM);
    cudaFuncSetAttribute(attn_h, cudaFuncAttributeMaxDynamicSharedMemorySize, ATTN_SMEM);

    // Fused weight transpose/convert (one launch) + bias concat.
    transpose_all_kernel<<<2816, dim3(32, 8)>>>(Wq, Wk, Wv, W1, W2, wqkv, w1t, w2t);
    concat_bias_kernel<<<1, 512>>>(bq, bk, bv, bqkv);

    // LN1 -> half
    ln_kernel<<<NROWS, 256>>>(x, g1, be1, xn1);
    // Fused QKV projection (Q,K: [B,H,S,Dh]; V: [B,H,Dh,S])
    gemm_h<<<dim3(12, 64), 256, GEMM_SMEM>>>(xn1, wqkv, bqkv, nullptr, qb, 512, 1536, 0);
    // Sigmoid attention + residual -> x1 (fp32)
    attn_h<<<dim3(16, 8, 4), 512, ATTN_SMEM>>>(qb, kb, vb, x, x1);
    // LN2 -> half
    ln_kernel<<<NROWS, 256>>>(x1, g2, be2, xn2);
    // FFN
    gemm_h<<<dim3(16, 64), 256, GEMM_SMEM>>>(xn2, w1t, b1, nullptr, mid, 512, 2048, 1);
    gemm_h<<<dim3(4, 64), 256, GEMM_SMEM>>>(mid, w2t, b2, x1, out, 2048, 512, 2);
}

// round 11
// speedup vs baseline: 6.6413x; 1.0731x over previous
#include <cuda_runtime.h>
#include <cuda_fp16.h>
#include <math.h>
#include <stdint.h>

// Problem constants
#define D_MODEL 512
#define N_HEADS 8
#define DH      64
#define D_FF    2048
#define BATCH   4
#define SEQ     2048
#define NROWS   (BATCH*SEQ)   // 8192

// ---------------------------------------------------------------------------
// Scratch (allocation-free rule). Offsets in floats; half buffers reinterpret.
// ---------------------------------------------------------------------------
__device__ __align__(256) float g_scratch[25165824];

#define OFF_XN1  0u          // half [8192][512]
#define OFF_Q    2097152u    // half [B][H][S][Dh]
#define OFF_K    4194304u    // half [B][H][S][Dh]
#define OFF_V    6291456u    // half [B][H][Dh][S]  (transposed!)
#define OFF_X1   8388608u    // float [8192][512]
#define OFF_XN2  12582912u   // half [8192][512]
#define OFF_MID  14680064u   // half [8192][2048]
#define OFF_WQKV 23068672u   // half [1536][512]  (transposed [out][in], Q|K|V)
#define OFF_W1   23461888u   // half [2048][512]
#define OFF_W2   23986176u   // half [512][2048]
#define OFF_BQKV 24510464u   // float [1536]

// ---------------------------------------------------------------------------
// Helpers
// ---------------------------------------------------------------------------
__device__ __forceinline__ void mma_f16(float* d, const uint32_t* a, const uint32_t* b) {
    asm volatile(
        "mma.sync.aligned.m16n8k16.row.col.f32.f16.f16.f32 "
        "{%0,%1,%2,%3}, {%4,%5,%6,%7}, {%8,%9}, {%0,%1,%2,%3};\n"
        : "+f"(d[0]), "+f"(d[1]), "+f"(d[2]), "+f"(d[3])
        : "r"(a[0]), "r"(a[1]), "r"(a[2]), "r"(a[3]), "r"(b[0]), "r"(b[1]));
}

__device__ __forceinline__ void ldsm_x4(uint32_t* r, uint32_t addr) {
    asm volatile("ldmatrix.sync.aligned.m8n8.x4.shared.b16 {%0,%1,%2,%3}, [%4];"
        : "=r"(r[0]), "=r"(r[1]), "=r"(r[2]), "=r"(r[3]) : "r"(addr));
}
__device__ __forceinline__ void ldsm_x2(uint32_t* r, uint32_t addr) {
    asm volatile("ldmatrix.sync.aligned.m8n8.x2.shared.b16 {%0,%1}, [%2];"
        : "=r"(r[0]), "=r"(r[1]) : "r"(addr));
}

__device__ __forceinline__ uint32_t sigmoid_h2(float z0, float z1) {
    // sigmoid(z) = 0.5 + 0.5*tanh(0.5*z); inputs are already 0.5*scale*score
    __half2 hz = __floats2half2_rn(z0, z1);
    uint32_t u = *(uint32_t*)&hz;
    uint32_t t;
    asm("tanh.approx.f16x2 %0, %1;" : "=r"(t) : "r"(u));
    __half2 th = *(__half2*)&t;
    __half2 r = __hfma2(th, __float2half2_rn(0.5f), __float2half2_rn(0.5f));
    return *(uint32_t*)&r;
}

__device__ __forceinline__ void cpasync16(uint32_t s, const void* g) {
    asm volatile("cp.async.cg.shared.global [%0], [%1], 16;" :: "r"(s), "l"(g));
}
__device__ __forceinline__ void cpcommit() { asm volatile("cp.async.commit_group;"); }
__device__ __forceinline__ void cpwait0()  { asm volatile("cp.async.wait_group 0;"); }
__device__ __forceinline__ void cpwait1()  { asm volatile("cp.async.wait_group 1;"); }

__device__ __forceinline__ uint32_t smem_u32(const void* p) {
    return (uint32_t)__cvta_generic_to_shared(p);
}

// ---------------------------------------------------------------------------
// Fused weight convert + transpose: 5 weights, one launch.
// ---------------------------------------------------------------------------
__global__ __launch_bounds__(256) void transpose_all_kernel(
    const float* __restrict__ Wq, const float* __restrict__ Wk,
    const float* __restrict__ Wv, const float* __restrict__ W1,
    const float* __restrict__ W2,
    __half* __restrict__ wqkv, __half* __restrict__ w1t, __half* __restrict__ w2t)
{
    __shared__ float t[32][33];
    int tb = blockIdx.x;
    const float* W; __half* Wt; int K, M, mcols;
    if (tb < 768) {
        int wsel = tb >> 8; tb &= 255;
        W = (wsel == 0) ? Wq : (wsel == 1) ? Wk : Wv;
        Wt = wqkv + (size_t)wsel * 262144u;
        K = 512; M = 512; mcols = 16;
    } else if (tb < 1792) {
        tb -= 768; W = W1; Wt = w1t; K = 512; M = 2048; mcols = 64;
    } else {
        tb -= 1792; W = W2; Wt = w2t; K = 2048; M = 512; mcols = 16;
    }
    int m0 = (tb % mcols) * 32, k0 = (tb / mcols) * 32;
    int tx = threadIdx.x, ty = threadIdx.y;
    #pragma unroll
    for (int j = 0; j < 4; j++) {
        int kr = ty + j * 8;
        t[kr][tx] = W[(size_t)(k0 + kr) * M + m0 + tx];
    }
    __syncthreads();
    #pragma unroll
    for (int j = 0; j < 4; j++) {
        int mr = ty + j * 8;
        Wt[(size_t)(m0 + mr) * K + k0 + tx] = __float2half(t[tx][mr]);
    }
}

// Concat three 512-float bias vectors.
__global__ __launch_bounds__(512) void concat_bias_kernel(
    const float* __restrict__ a, const float* __restrict__ b,
    const float* __restrict__ c, float* __restrict__ o)
{
    int t = threadIdx.x;
    o[t] = a[t]; o[512 + t] = b[t]; o[1024 + t] = c[t];
}

// ---------------------------------------------------------------------------
// LayerNorm: block per row, 256 threads, half output.
// ---------------------------------------------------------------------------
__global__ __launch_bounds__(256) void ln_kernel(
    const float* __restrict__ x, const float* __restrict__ g,
    const float* __restrict__ b, __half* __restrict__ y)
{
    int row = blockIdx.x;
    int t = threadIdx.x;
    const float2* xr = (const float2*)(x + (size_t)row * D_MODEL);
    __half2* yr = (__half2*)(y + (size_t)row * D_MODEL);
    float2 v = xr[t];

    __shared__ float red[8];

    float s = v.x + v.y;
    #pragma unroll
    for (int o = 16; o > 0; o >>= 1) s += __shfl_xor_sync(0xffffffffu, s, o);
    if ((t & 31) == 0) red[t >> 5] = s;
    __syncthreads();
    float tot = 0.f;
    #pragma unroll
    for (int i = 0; i < 8; i++) tot += red[i];
    float mu = tot * (1.0f / D_MODEL);
    __syncthreads();

    float d0 = v.x - mu, d1 = v.y - mu;
    s = d0 * d0 + d1 * d1;
    #pragma unroll
    for (int o = 16; o > 0; o >>= 1) s += __shfl_xor_sync(0xffffffffu, s, o);
    if ((t & 31) == 0) red[t >> 5] = s;
    __syncthreads();
    tot = 0.f;
    #pragma unroll
    for (int i = 0; i < 8; i++) tot += red[i];
    float inv = rsqrtf(tot * (1.0f / D_MODEL) + 1e-5f);

    float2 gg = ((const float2*)g)[t];
    float2 bb = ((const float2*)b)[t];
    yr[t] = __floats2half2_rn(d0 * inv * gg.x + bb.x, d1 * inv * gg.y + bb.y);
}

// ---------------------------------------------------------------------------
// FP16 tensor-core GEMM with ldmatrix fragment loads.
// 128x128x32 block tile, 256 threads (8 warps, 2x4), 64x32 warp tiles,
// m16n8k16, cp.async double-buffered. Smem stride 40 halves (80B rows:
// 8-row x 16B ldmatrix fetches land on distinct 16B banks mod 128).
// ---------------------------------------------------------------------------
#define SH 40
#define GEMM_SMEM (2*(2*128*SH*2))   // 40960 B

__global__ __launch_bounds__(256, 2) void gemm_h(
    const __half* __restrict__ A, const __half* __restrict__ Wt,
    const float* __restrict__ bias, const float* __restrict__ resid,
    void* __restrict__ Cv, int K, int M, int mode)
{
    extern __shared__ __half sm[];
    __half* As = sm;                 // [2][128][SH]
    __half* Bs = sm + 2 * 128 * SH;  // [2][128][SH]

    int tid = threadIdx.x;
    int w = tid >> 5, lane = tid & 31;
    int g = lane >> 2, t4 = lane & 3;
    int wr = w >> 2, wc = w & 3;
    int rowBase = blockIdx.y * 128;
    int colBase = blockIdx.x * 128;

    uint32_t sA = smem_u32(As);
    uint32_t sB = smem_u32(Bs);

    // ldmatrix per-lane base offsets (bytes)
    uint32_t aOff = ((wr * 64 + (lane & 15)) * SH + 8 * (lane >> 4)) * 2;
    uint32_t bOff = ((wc * 32 + (lane & 7)) * SH + 8 * ((lane >> 3) & 1)) * 2;

    float acc[4][4][4];
    #pragma unroll
    for (int mf = 0; mf < 4; mf++)
        #pragma unroll
        for (int nf = 0; nf < 4; nf++)
            #pragma unroll
            for (int r = 0; r < 4; r++) acc[mf][nf][r] = 0.f;

    int rr[2], rc[2];
    #pragma unroll
    for (int j = 0; j < 2; j++) {
        int i = tid + 256 * j;
        rr[j] = i >> 2; rc[j] = (i & 3) * 8;
    }

    int nk = K >> 5;

    #pragma unroll
    for (int j = 0; j < 2; j++) {
        cpasync16(sA + (rr[j] * SH + rc[j]) * 2, A + (size_t)(rowBase + rr[j]) * K + rc[j]);
        cpasync16(sB + (rr[j] * SH + rc[j]) * 2, Wt + (size_t)(colBase + rr[j]) * K + rc[j]);
    }
    cpcommit();

    for (int it = 0; it < nk; it++) {
        cpwait0();
        __syncthreads();
        if (it + 1 < nk) {
            int k0 = (it + 1) << 5;
            int buf = (it + 1) & 1;
            #pragma unroll
            for (int j = 0; j < 2; j++) {
                cpasync16(sA + (buf * 128 * SH + rr[j] * SH + rc[j]) * 2,
                          A + (size_t)(rowBase + rr[j]) * K + k0 + rc[j]);
                cpasync16(sB + (buf * 128 * SH + rr[j] * SH + rc[j]) * 2,
                          Wt + (size_t)(colBase + rr[j]) * K + k0 + rc[j]);
            }
            cpcommit();
        }
        uint32_t aB = sA + aOff + (it & 1) * 128 * SH * 2;
        uint32_t bB = sB + bOff + (it & 1) * 128 * SH * 2;

        #pragma unroll
        for (int ks = 0; ks < 32; ks += 16) {
            uint32_t a[4][4], bf[4][2];
            #pragma unroll
            for (int mf = 0; mf < 4; mf++)
                ldsm_x4(a[mf], aB + (mf * 16 * SH + ks) * 2);
            #pragma unroll
            for (int nf = 0; nf < 4; nf++)
                ldsm_x2(bf[nf], bB + (nf * 8 * SH + ks) * 2);
            #pragma unroll
            for (int mf = 0; mf < 4; mf++)
                #pragma unroll
                for (int nf = 0; nf < 4; nf++)
                    mma_f16(acc[mf][nf], a[mf], bf[nf]);
        }
        // NOTE: no end-of-loop sync needed — next iteration's top barrier
        // (after cpwait0) orders buffer reuse.
    }

    // Epilogue
    #pragma unroll
    for (int mf = 0; mf < 4; mf++) {
        int r0 = rowBase + wr * 64 + mf * 16 + g;
        #pragma unroll
        for (int nf = 0; nf < 4; nf++) {
            int c0 = colBase + wc * 32 + nf * 8 + 2 * t4;
            float b0 = bias[c0], b1 = bias[c0 + 1];
            #pragma unroll
            for (int half_ = 0; half_ < 2; half_++) {
                int row = r0 + half_ * 8;
                float v0 = acc[mf][nf][half_ * 2 + 0] + b0;
                float v1 = acc[mf][nf][half_ * 2 + 1] + b1;
                if (mode == 0) {
                    int proj = c0 >> 9;
                    int cl = c0 & 511;
                    int b_ = row >> 11, s = row & 2047, h = cl >> 6, d = cl & 63;
                    __half* base = (__half*)Cv + (size_t)proj * 4194304u;
                    if (proj < 2) {
                        __half2* C = (__half2*)(base +
                            ((((size_t)b_ * N_HEADS + h) * SEQ + s) * DH + d));
                        *C = __floats2half2_rn(v0, v1);
                    } else {
                        size_t vo = (((size_t)b_ * N_HEADS + h) * DH + d) * SEQ + s;
                        base[vo] = __float2half(v0);
                        base[vo + SEQ] = __float2half(v1);
                    }
                } else if (mode == 1) {
                    __half2* C = (__half2*)((__half*)Cv + (size_t)row * M + c0);
                    *C = __floats2half2_rn(fmaxf(v0, 0.f), fmaxf(v1, 0.f));
                } else {
                    float2 rv = *(const float2*)(resid + (size_t)row * M + c0);
                    *(float2*)((float*)Cv + (size_t)row * M + c0) =
                        make_float2(v0 + rv.x, v1 + rv.y);
                }
            }
        }
    }
}

// ---------------------------------------------------------------------------
// Sigmoid-pointwise attention, fp16 tensor cores + cp.async pipelining +
// ldmatrix fragment loads. Strides AQ (144B) / AV (272B) are conflict-free
// for 8x16B ldmatrix row fetches.
// ---------------------------------------------------------------------------
#define AQ 72
#define AV 136
#define ATTN_SMEM ((128*AQ + 2*128*AQ + 64*AV + 128*AV) * 2)   // 107520

__global__ __launch_bounds__(512, 2) void attn_h(
    const __half* __restrict__ q, const __half* __restrict__ kk,
    const __half* __restrict__ vv, const float* __restrict__ x,
    float* __restrict__ x1)
{
    extern __shared__ __half sm[];
    __half* Qs = sm;                     // [128][AQ]  [s][d]
    __half* Ks = Qs + 128 * AQ;          // [2][128][AQ]  [t][d]
    __half* Vs = Ks + 2 * 128 * AQ;      // [64][AV]   [d][t]
    __half* Ps = Vs + 64 * AV;           // [128][AV]  [s][t]

    int b = blockIdx.z, h = blockIdx.y;
    int s0 = blockIdx.x * 128;
    const __half* qbase = q + (((size_t)b * N_HEADS + h) * SEQ + s0) * DH;
    const __half* kbase = kk + ((size_t)b * N_HEADS + h) * SEQ * DH;
    const __half* vbase = vv + ((size_t)b * N_HEADS + h) * DH * SEQ;

    int tid = threadIdx.x, w = tid >> 5, lane = tid & 31;
    int g = lane >> 2, t4 = lane & 3;
    int wr1 = w >> 2, wc1 = w & 3;   // mm1: 4x4 grid of 32x32
    int wr2 = w >> 1, wc2 = w & 1;   // mm2: 8x2 grid of 16x32

    uint32_t qS = smem_u32(Qs);
    uint32_t kS = smem_u32(Ks);
    uint32_t vS = smem_u32(Vs);
    uint32_t pS = smem_u32(Ps);

    // ldmatrix per-lane base offsets (bytes)
    uint32_t qaOff = qS + ((wr1 * 32 + (lane & 15)) * AQ + 8 * (lane >> 4)) * 2;
    uint32_t kbOff = ((wc1 * 32 + (lane & 7)) * AQ + 8 * ((lane >> 3) & 1)) * 2;
    uint32_t paOff = pS + ((wr2 * 16 + (lane & 15)) * AV + 8 * (lane >> 4)) * 2;
    uint32_t vbOff = vS + ((wc2 * 32 + (lane & 7)) * AV + 8 * ((lane >> 3) & 1)) * 2;

    // indices for async loads (2 chunks of 16B each for K and for V)
    int kr[2], kc[2], vd[2], vc[2];
    #pragma unroll
    for (int j = 0; j < 2; j++) {
        int i = tid + 512 * j;
        kr[j] = i >> 3;  kc[j] = (i & 7) * 8;     // 128 rows x 8 chunks
        vd[j] = i >> 4;  vc[j] = (i & 15) * 8;    // 64 rows x 16 chunks
    }

    // Prologue: Q + K(0) in group A; V(0) in group B.
    #pragma unroll
    for (int j = 0; j < 2; j++) {
        cpasync16(qS + (kr[j] * AQ + kc[j]) * 2, qbase + (size_t)kr[j] * DH + kc[j]);
        cpasync16(kS + (kr[j] * AQ + kc[j]) * 2, kbase + (size_t)kr[j] * DH + kc[j]);
    }
    cpcommit();
    #pragma unroll
    for (int j = 0; j < 2; j++)
        cpasync16(vS + (vd[j] * AV + vc[j]) * 2, vbase + (size_t)vd[j] * SEQ + vc[j]);
    cpcommit();

    float o[4][4];
    #pragma unroll
    for (int nf = 0; nf < 4; nf++)
        #pragma unroll
        for (int r = 0; r < 4; r++) o[nf][r] = 0.f;

    const float hscale = 0.5f * 0.04419417382415922f;  // 0.5/sqrt(512)

    int buf = 0;
    for (int t0 = 0; t0 < SEQ; t0 += 128) {
        bool more = (t0 + 128 < SEQ);
        cpwait1();
        __syncthreads();

        // Prefetch K(t+1) into other buffer.
        if (more) {
            uint32_t kd = kS + (buf ^ 1) * 128 * AQ * 2;
            #pragma unroll
            for (int j = 0; j < 2; j++)
                cpasync16(kd + (kr[j] * AQ + kc[j]) * 2,
                          kbase + (size_t)(t0 + 128 + kr[j]) * DH + kc[j]);
            cpcommit();
        }

        uint32_t kB = kS + kbOff + buf * 128 * AQ * 2;

        // mm1: P = Q K^T
        float p[2][4][4];
        #pragma unroll
        for (int mf = 0; mf < 2; mf++)
            #pragma unroll
            for (int nf = 0; nf < 4; nf++)
                #pragma unroll
                for (int r = 0; r < 4; r++) p[mf][nf][r] = 0.f;

        #pragma unroll
        for (int ks = 0; ks < 64; ks += 16) {
            uint32_t a[2][4], bf[4][2];
            #pragma unroll
            for (int mf = 0; mf < 2; mf++)
                ldsm_x4(a[mf], qaOff + (mf * 16 * AQ + ks) * 2);
            #pragma unroll
            for (int nf = 0; nf < 4; nf++)
                ldsm_x2(bf[nf], kB + (nf * 8 * AQ + ks) * 2);
            #pragma unroll
            for (int mf = 0; mf < 2; mf++)
                #pragma unroll
                for (int nf = 0; nf < 4; nf++)
                    mma_f16(p[mf][nf], a[mf], bf[nf]);
        }

        // sigmoid via tanh.approx.f16x2 -> half2 Ps[s][t]
        #pragma unroll
        for (int mf = 0; mf < 2; mf++) {
            int r0 = wr1 * 32 + mf * 16 + g;
            #pragma unroll
            for (int nf = 0; nf < 4; nf++) {
                int c0 = wc1 * 32 + nf * 8 + 2 * t4;
                #pragma unroll
                for (int half_ = 0; half_ < 2; half_++) {
                    int rw = r0 + half_ * 8;
                    uint32_t r2 = sigmoid_h2(p[mf][nf][half_ * 2 + 0] * hscale,
                                             p[mf][nf][half_ * 2 + 1] * hscale);
                    *(uint32_t*)(Ps + rw * AV + c0) = r2;
                }
            }
        }

        if (more) cpwait1(); else cpwait0();
        __syncthreads();   // Ps + Vs visible

        // mm2: O += P V
        #pragma unroll
        for (int ks = 0; ks < 128; ks += 16) {
            uint32_t a[4], bf[4][2];
            ldsm_x4(a, paOff + ks * 2);
            #pragma unroll
            for (int nf = 0; nf < 4; nf++)
                ldsm_x2(bf[nf], vbOff + (nf * 8 * AV + ks) * 2);
            #pragma unroll
            for (int nf = 0; nf < 4; nf++)
                mma_f16(o[nf], a, bf[nf]);
        }

        __syncthreads();   // everyone done reading Vs (and Ps)

        // Issue V(t+1); completes during next tile's mm1.
        if (more) {
            #pragma unroll
            for (int j = 0; j < 2; j++)
                cpasync16(vS + (vd[j] * AV + vc[j]) * 2,
                          vbase + (size_t)vd[j] * SEQ + t0 + 128 + vc[j]);
            cpcommit();
        }
        buf ^= 1;
    }

    // Epilogue: x1 = x + O
    int r0 = wr2 * 16 + g;
    #pragma unroll
    for (int nf = 0; nf < 4; nf++) {
        int col = h * DH + wc2 * 32 + nf * 8 + 2 * t4;
        #pragma unroll
        for (int half_ = 0; half_ < 2; half_++) {
            int s = s0 + r0 + half_ * 8;
            size_t idx = ((size_t)(b * SEQ + s)) * D_MODEL + col;
            float2 xr = *(const float2*)(x + idx);
            *(float2*)(x1 + idx) = make_float2(xr.x + o[nf][half_ * 2 + 0],
                                               xr.y + o[nf][half_ * 2 + 1]);
        }
    }
}

// ---------------------------------------------------------------------------
// kernel_launch
// ---------------------------------------------------------------------------
extern "C" void kernel_launch(void* const* d_in, const int* in_sizes, int n_in,
                              void* d_out, int out_size)
{
    (void)in_sizes; (void)n_in; (void)out_size;
    const float* x   = (const float*)d_in[0];
    const float* Wq  = (const float*)d_in[1];
    const float* bq  = (const float*)d_in[2];
    const float* Wk  = (const float*)d_in[3];
    const float* bk  = (const float*)d_in[4];
    const float* Wv  = (const float*)d_in[5];
    const float* bv  = (const float*)d_in[6];
    const float* W1  = (const float*)d_in[7];
    const float* b1  = (const float*)d_in[8];
    const float* W2  = (const float*)d_in[9];
    const float* b2  = (const float*)d_in[10];
    const float* g1  = (const float*)d_in[11];
    const float* be1 = (const float*)d_in[12];
    const float* g2  = (const float*)d_in[13];
    const float* be2 = (const float*)d_in[14];
    float* out = (float*)d_out;

    float* scratch = nullptr;
    cudaGetSymbolAddress((void**)&scratch, g_scratch);
    __half* xn1 = (__half*)(scratch + OFF_XN1);
    __half* qb  = (__half*)(scratch + OFF_Q);
    __half* kb  = (__half*)(scratch + OFF_K);
    __half* vb  = (__half*)(scratch + OFF_V);
    float*  x1  = scratch + OFF_X1;
    __half* xn2 = (__half*)(scratch + OFF_XN2);
    __half* mid = (__half*)(scratch + OFF_MID);
    __half* wqkv = (__half*)(scratch + OFF_WQKV);
    __half* w1t = (__half*)(scratch + OFF_W1);
    __half* w2t = (__half*)(scratch + OFF_W2);
    float*  bqkv = scratch + OFF_BQKV;

    cudaFuncSetAttribute(gemm_h, cudaFuncAttributeMaxDynamicSharedMemorySize, GEMM_SMEM);
    cudaFuncSetAttribute(attn_h, cudaFuncAttributeMaxDynamicSharedMemorySize, ATTN_SMEM);

    // Fused weight transpose/convert (one launch) + bias concat.
    transpose_all_kernel<<<2816, dim3(32, 8)>>>(Wq, Wk, Wv, W1, W2, wqkv, w1t, w2t);
    concat_bias_kernel<<<1, 512>>>(bq, bk, bv, bqkv);

    // LN1 -> half
    ln_kernel<<<NROWS, 256>>>(x, g1, be1, xn1);
    // Fused QKV projection (Q,K: [B,H,S,Dh]; V: [B,H,Dh,S])
    gemm_h<<<dim3(12, 64), 256, GEMM_SMEM>>>(xn1, wqkv, bqkv, nullptr, qb, 512, 1536, 0);
    // Sigmoid attention + residual -> x1 (fp32)
    attn_h<<<dim3(16, 8, 4), 512, ATTN_SMEM>>>(qb, kb, vb, x, x1);
    // LN2 -> half
    ln_kernel<<<NROWS, 256>>>(x1, g2, be2, xn2);
    // FFN
    gemm_h<<<dim3(16, 64), 256, GEMM_SMEM>>>(xn2, w1t, b1, nullptr, mid, 512, 2048, 1);
    gemm_h<<<dim3(4, 64), 256, GEMM_SMEM>>>(mid, w2t, b2, x1, out, 2048, 512, 2);
}